// round 15
// baseline (speedup 1.0000x reference)
#include <cuda_runtime.h>
#include <cuda_fp16.h>
#include <math.h>
#include <stdint.h>

// Problem constants
#define S_LEN 2048
#define DM    512
#define NH    8
#define DH    64
#define MF    64
#define DFF   2048
#define NL    2
#define NC    64
#define CHUNK 32
#define EPS_A 1e-6f
#define LN_EPS 1e-5f
#define NQKV  1536

// ---------------- scratch ----------------
__device__ float g_X [S_LEN*DM];
__device__ float g_T0[S_LEN*DM];
__device__ float g_T1[S_LEN*DM];
__device__ float g_QKV[S_LEN*NQKV];
__device__ float g_PQ[S_LEN*DM];
__device__ float g_PK[S_LEN*DM];
__device__ float g_KVs[NH*NC*DH*DH];
__device__ float g_KVp[NH*NC*DH*DH];
__device__ float g_Ks [NH*NC*DH];
__device__ float g_Ksp[NH*NC*DH];

// packed fp16 hi/lo operand buffers (K-major: [K/2][M])
__device__ uint32_t g_XpH[(DM/2)*S_LEN],  g_XpL[(DM/2)*S_LEN];
__device__ uint32_t g_ApH[(DM/2)*S_LEN],  g_ApL[(DM/2)*S_LEN];
__device__ uint32_t g_FpH[(DFF/2)*S_LEN], g_FpL[(DFF/2)*S_LEN];
__device__ uint32_t g_WqkvH[NL*(DM/2)*NQKV], g_WqkvL[NL*(DM/2)*NQKV];
__device__ uint32_t g_WoH[NL*(DM/2)*DM],  g_WoL[NL*(DM/2)*DM];
__device__ uint32_t g_W1H[NL*(DM/2)*DFF], g_W1L[NL*(DM/2)*DFF];
__device__ uint32_t g_W2H[NL*(DFF/2)*DM], g_W2L[NL*(DFF/2)*DM];
__device__ float    g_bqkv[NL*NQKV];

// ---------------- helpers ----------------
__device__ __forceinline__ uint32_t smem_u32(const void* p) {
    uint32_t a;
    asm("{ .reg .u64 t; cvta.to.shared.u64 t, %1; cvt.u32.u64 %0, t; }" : "=r"(a) : "l"(p));
    return a;
}
__device__ __forceinline__ void cp16(uint32_t dst, const void* src) {
    asm volatile("cp.async.ca.shared.global [%0], [%1], 16;" :: "r"(dst), "l"(src));
}
__device__ __forceinline__ void mma16816(float* d, const uint32_t* a,
                                         uint32_t b0, uint32_t b1) {
    asm volatile(
        "mma.sync.aligned.m16n8k16.row.col.f32.f16.f16.f32 "
        "{%0,%1,%2,%3}, {%4,%5,%6,%7}, {%8,%9}, {%0,%1,%2,%3};"
        : "+f"(d[0]), "+f"(d[1]), "+f"(d[2]), "+f"(d[3])
        : "r"(a[0]), "r"(a[1]), "r"(a[2]), "r"(a[3]), "r"(b0), "r"(b1));
}
__device__ __forceinline__ void pack_hl(float v0, float v1, uint32_t& hi, uint32_t& lo) {
    __half h0 = __float2half_rn(v0), h1 = __float2half_rn(v1);
    __half l0 = __float2half_rn(v0 - __half2float(h0));
    __half l1 = __float2half_rn(v1 - __half2float(h1));
    __half2 H = __halves2half2(h0, h1), L = __halves2half2(l0, l1);
    hi = *(uint32_t*)&H; lo = *(uint32_t*)&L;
}

// ---------------- merged weight pack ---------------------------------------------------
struct PackJobs {
    const float* src[NL * 6];
    uint32_t*    dstH[NL * 6];
    uint32_t*    dstL[NL * 6];
    int          ostr[NL * 6];
};
__global__ __launch_bounds__(256) void pack_all(PackJobs jobs) {
    int b = blockIdx.x;
    int l = b / 1536, r = b % 1536;
    int seg, local, N;
    if (r < 512)       { seg = r >> 7; local = r & 127;  N = DM;  }
    else if (r < 1024) { seg = 4;      local = r - 512;  N = DFF; }
    else               { seg = 5;      local = r - 1024; N = DM;  }
    int j = l * 6 + seg;
    const float* W = jobs.src[j];
    uint32_t* WH = jobs.dstH[j];
    uint32_t* WL = jobs.dstL[j];
    int ostr = jobs.ostr[j];
    int idx = local * 256 + threadIdx.x;
    int n4 = N / 4;
    int k2 = idx / n4;
    int n  = (idx % n4) * 4;
    float4 r0 = *(const float4*)(W + (size_t)(2 * k2) * N + n);
    float4 r1 = *(const float4*)(W + (size_t)(2 * k2 + 1) * N + n);
    uint4 H, L;
    pack_hl(r0.x, r1.x, H.x, L.x);
    pack_hl(r0.y, r1.y, H.y, L.y);
    pack_hl(r0.z, r1.z, H.z, L.z);
    pack_hl(r0.w, r1.w, H.w, L.w);
    *(uint4*)(WH + (size_t)k2 * ostr + n) = H;
    *(uint4*)(WL + (size_t)k2 * ostr + n) = L;
}

__global__ __launch_bounds__(256) void bias_qkv(
    const float* __restrict__ bq, const float* __restrict__ bk,
    const float* __restrict__ bv, float* __restrict__ out)
{
    int idx = blockIdx.x * 256 + threadIdx.x;
    int l = idx / NQKV, c = idx % NQKV;
    const float* src = (c < 512) ? bq : ((c < 1024) ? bk : bv);
    out[idx] = src[l * DM + (c & 511)];
}

// ---------------- activation pack (transpose): fp32 [M][K] -> [K/2][2048] ---------------
__global__ __launch_bounds__(256) void pack_act(
    const float* __restrict__ in, uint32_t* __restrict__ outH,
    uint32_t* __restrict__ outL, int K)
{
    __shared__ float s[32][33];
    int m0 = blockIdx.y * 32, k0 = blockIdx.x * 32;
    int tid = threadIdx.x;
    int r = tid >> 5, c = tid & 31;
#pragma unroll
    for (int j = 0; j < 4; j++)
        s[r + 8 * j][c] = in[(size_t)(m0 + r + 8 * j) * K + k0 + c];
    __syncthreads();
    int k2l = tid >> 5, m = tid & 31;
#pragma unroll
    for (int j = 0; j < 2; j++) {
        int kk = k2l + 8 * j;
        float v0 = s[m][2 * kk], v1 = s[m][2 * kk + 1];
        uint32_t H, L;
        pack_hl(v0, v1, H, L);
        size_t o = (size_t)(k0 / 2 + kk) * S_LEN + m0 + m;
        outH[o] = H; outL[o] = L;
    }
}

// ---------------- fp16 split-precision GEMM core (tile 128 x NT, one sync/chunk) --------
template<int NT, int MODE>
__device__ __forceinline__ void hgemm_core(
    const uint32_t* __restrict__ Ahi, const uint32_t* __restrict__ Alo,
    const uint32_t* __restrict__ Bhi, const uint32_t* __restrict__ Blo,
    const float* __restrict__ bias,
    float* __restrict__ C, uint32_t* __restrict__ CpH, uint32_t* __restrict__ CpL,
    int N, int K, uint32_t* sm)
{
    constexpr int ASTR = 136;
    constexpr int BSTR = NT + 8;
    constexpr int ASM  = 16 * ASTR;
    constexpr int BSM  = 16 * BSTR;
    constexpr int STG  = 2 * ASM + 2 * BSM;
    constexpr int NFR  = NT / 16;
    constexpr int M    = S_LEN;

    const uint32_t smb = smem_u32(sm);
    const int tid = threadIdx.x;
    const int wid = tid >> 5, lane = tid & 31;
    const int lq = lane >> 2, lr = lane & 3;
    const int m0 = blockIdx.y * 128;
    const int n0 = blockIdx.x * NT;
    const int wm = (wid & 3) * 32;
    const int wn = (wid >> 2) * (NT / 2);

    float acc[2][NFR][4];
#pragma unroll
    for (int mi = 0; mi < 2; mi++)
#pragma unroll
        for (int ni = 0; ni < NFR; ni++)
#pragma unroll
            for (int e = 0; e < 4; e++) acc[mi][ni][e] = 0.f;

    const int KCH = K / 32;

#define PREFETCH(cc, ss) do {                                                  \
    uint32_t base = smb + (uint32_t)(ss) * STG * 4;                            \
    const uint32_t* Ah = Ahi + (size_t)((cc) * 16) * M + m0;                   \
    const uint32_t* Al = Alo + (size_t)((cc) * 16) * M + m0;                   \
    _Pragma("unroll")                                                          \
    for (int i = 0; i < 2; i++) {                                              \
        int idx = tid + i * 256; int rr = idx >> 5; int c4 = (idx & 31) * 4;   \
        cp16(base + (uint32_t)(rr * ASTR + c4) * 4, Ah + (size_t)rr * M + c4); \
        cp16(base + (uint32_t)(ASM + rr * ASTR + c4) * 4, Al + (size_t)rr * M + c4); \
    }                                                                          \
    const uint32_t* Bh = Bhi + (size_t)((cc) * 16) * N + n0;                   \
    const uint32_t* Bl = Blo + (size_t)((cc) * 16) * N + n0;                   \
    _Pragma("unroll")                                                          \
    for (int i = 0; i < NT / 64; i++) {                                        \
        int idx = tid + i * 256; int rr = idx / (NT / 4); int c4 = (idx % (NT / 4)) * 4; \
        cp16(base + (uint32_t)(2 * ASM + rr * BSTR + c4) * 4, Bh + (size_t)rr * N + c4); \
        cp16(base + (uint32_t)(2 * ASM + BSM + rr * BSTR + c4) * 4, Bl + (size_t)rr * N + c4); \
    }                                                                          \
    asm volatile("cp.async.commit_group;" ::: "memory");                       \
} while (0)

    PREFETCH(0, 0);

    for (int c = 0; c < KCH; c++) {
        const int s = c & 1;
        asm volatile("cp.async.wait_group 0;" ::: "memory");
        __syncthreads();
        if (c + 1 < KCH) PREFETCH(c + 1, s ^ 1);

        const uint32_t* sAh = sm + s * STG;
        const uint32_t* sAl = sAh + ASM;
        const uint32_t* sBh = sAh + 2 * ASM;
        const uint32_t* sBl = sBh + BSM;

#pragma unroll
        for (int st = 0; st < 2; st++) {
            const int kb = st * 8;
            uint32_t ah[2][4], al[2][4];
#pragma unroll
            for (int mi = 0; mi < 2; mi++) {
                int m = wm + mi * 16 + lq;
                int i0 = (kb + lr) * ASTR + m;
                int i1 = (kb + 4 + lr) * ASTR + m;
                ah[mi][0] = sAh[i0];     ah[mi][1] = sAh[i0 + 8];
                ah[mi][2] = sAh[i1];     ah[mi][3] = sAh[i1 + 8];
                al[mi][0] = sAl[i0];     al[mi][1] = sAl[i0 + 8];
                al[mi][2] = sAl[i1];     al[mi][3] = sAl[i1 + 8];
            }
#pragma unroll
            for (int ni = 0; ni < NFR; ni++) {
                int n = wn + ni * 8 + lq;
                int j0 = (kb + lr) * BSTR + n;
                int j1 = (kb + 4 + lr) * BSTR + n;
                uint32_t bh0 = sBh[j0], bh1 = sBh[j1];
                uint32_t bl0 = sBl[j0], bl1 = sBl[j1];
#pragma unroll
                for (int mi = 0; mi < 2; mi++) {
                    mma16816(acc[mi][ni], ah[mi], bh0, bh1);
                    mma16816(acc[mi][ni], ah[mi], bl0, bl1);
                    mma16816(acc[mi][ni], al[mi], bh0, bh1);
                }
            }
        }
        // no trailing sync (2-stage: next top sync orders compute(s) vs prefetch->s)
    }
#undef PREFETCH

#pragma unroll
    for (int mi = 0; mi < 2; mi++) {
        int r = m0 + wm + mi * 16 + lq;
#pragma unroll
        for (int ni = 0; ni < NFR; ni++) {
            int cc = n0 + wn + ni * 8 + lr * 2;
            float b0 = bias ? __ldg(bias + cc) : 0.f;
            float b1 = bias ? __ldg(bias + cc + 1) : 0.f;
            float v00 = acc[mi][ni][0] + b0, v01 = acc[mi][ni][1] + b1;
            float v10 = acc[mi][ni][2] + b0, v11 = acc[mi][ni][3] + b1;
            if (MODE == 0) {
                *(float2*)(C + (size_t)r * N + cc)       = make_float2(v00, v01);
                *(float2*)(C + (size_t)(r + 8) * N + cc) = make_float2(v10, v11);
            } else {
                v00 = fmaxf(v00, 0.f); v01 = fmaxf(v01, 0.f);
                v10 = fmaxf(v10, 0.f); v11 = fmaxf(v11, 0.f);
                uint32_t H0, L0, H1, L1;
                pack_hl(v00, v01, H0, L0);
                pack_hl(v10, v11, H1, L1);
                size_t o = (size_t)(cc >> 1) * M + r;
                CpH[o] = H0;     CpL[o] = L0;
                CpH[o + 8] = H1; CpL[o + 8] = L1;
            }
        }
    }
}

template<int NT, int MODE>
__global__ __launch_bounds__(256, (NT == 64) ? 3 : 2) void hgemm(
    const uint32_t* __restrict__ Ahi, const uint32_t* __restrict__ Alo,
    const uint32_t* __restrict__ Bhi, const uint32_t* __restrict__ Blo,
    const float* __restrict__ bias,
    float* __restrict__ C, uint32_t* __restrict__ CpH, uint32_t* __restrict__ CpL,
    int N, int K)
{
    extern __shared__ uint32_t sm[];
    hgemm_core<NT, MODE>(Ahi, Alo, Bhi, Blo, bias, C, CpH, CpL, N, K, sm);
}

// split-K x2 (NT=64): blockIdx.z selects K-half; z=0 gets bias; partials to C0/C1.
__global__ __launch_bounds__(256, 3) void hgemm_splitk(
    const uint32_t* __restrict__ Ahi, const uint32_t* __restrict__ Alo,
    const uint32_t* __restrict__ Bhi, const uint32_t* __restrict__ Blo,
    const float* __restrict__ bias,
    float* __restrict__ C0, float* __restrict__ C1,
    int N, int Kfull)
{
    extern __shared__ uint32_t sm[];
    const int Ksp = Kfull / 2;
    const int z = blockIdx.z;
    const size_t aoff = (size_t)z * (Ksp / 2) * S_LEN;
    const size_t boff = (size_t)z * (Ksp / 2) * N;
    hgemm_core<64, 0>(Ahi + aoff, Alo + aoff, Bhi + boff, Blo + boff,
                      z == 0 ? bias : nullptr,
                      z == 0 ? C0 : C1, nullptr, nullptr, N, Ksp, sm);
}

// ---------------- FAVOR+ feature map ----------------------------------------------------
__global__ __launch_bounds__(256) void favor_kernel(
    const float* __restrict__ QKV, const float* __restrict__ omega,
    float* __restrict__ PQ, float* __restrict__ PK)
{
    __shared__ float som[DH * MF];
    __shared__ float sx[8 * 8 * 64];
    float* P = blockIdx.y ? PK : PQ;
    const float* X = QKV + blockIdx.y * 512;
    int tid = threadIdx.x, w = tid >> 5, lane = tid & 31;
    for (int i = tid; i < DH * MF; i += 256) som[i] = omega[i];

    int s = blockIdx.x * 8 + w;
    const float SC = 0.35355339059327379f;
    const float* xrow = X + (size_t)s * NQKV;

    float nrm[8];
#pragma unroll
    for (int r = 0; r < 8; r++) {
        float x0 = xrow[r * 64 + lane] * SC;
        float x1 = xrow[r * 64 + 32 + lane] * SC;
        sx[w * 512 + r * 64 + lane] = x0;
        sx[w * 512 + r * 64 + 32 + lane] = x1;
        float n = x0 * x0 + x1 * x1;
#pragma unroll
        for (int o = 16; o; o >>= 1) n += __shfl_xor_sync(0xffffffffu, n, o);
        nrm[r] = n;
    }
    __syncthreads();

    float u0[8], u1[8];
#pragma unroll
    for (int r = 0; r < 8; r++) { u0[r] = 0.f; u1[r] = 0.f; }
#pragma unroll 8
    for (int d = 0; d < 64; d++) {
        float o0 = som[d * 64 + lane];
        float o1 = som[d * 64 + 32 + lane];
#pragma unroll
        for (int r = 0; r < 8; r++) {
            float xd = sx[w * 512 + r * 64 + d];
            u0[r] += xd * o0;
            u1[r] += xd * o1;
        }
    }
    float* prow = P + (size_t)s * DM;
#pragma unroll
    for (int r = 0; r < 8; r++) {
        float cst = -0.5f * nrm[r];
        prow[r * 64 + lane]      = expf(u0[r] + cst) * 0.125f;
        prow[r * 64 + 32 + lane] = expf(u1[r] + cst) * 0.125f;
    }
}

// ---------------- per-chunk sums ---------------------------------------------------------
__global__ __launch_bounds__(64) void chunk_sum_kernel(
    const float* __restrict__ PK, const float* __restrict__ QKV,
    float* __restrict__ KVs, float* __restrict__ Ks)
{
    __shared__ float spk[CHUNK * 64];
    __shared__ float sv [CHUNK * 64];
    int b = blockIdx.x;
    int h = b / NC, c = b % NC;
    int d = threadIdx.x;
    int s0 = c * CHUNK;
    for (int i = d; i < CHUNK * 64; i += 64) {
        int ss = i >> 6, e = i & 63;
        spk[i] = PK[(size_t)(s0 + ss) * DM + h * DH + e];
        sv[i]  = QKV[(size_t)(s0 + ss) * NQKV + 1024 + h * DH + e];
    }
    __syncthreads();
    float col[64];
#pragma unroll
    for (int m = 0; m < 64; m++) col[m] = 0.f;
    float ks = 0.f;
    for (int ss = 0; ss < CHUNK; ss++) {
        float vd = sv[ss * 64 + d];
        ks += spk[ss * 64 + d];
#pragma unroll
        for (int m = 0; m < 64; m++) col[m] += spk[ss * 64 + m] * vd;
    }
    float* out = KVs + (size_t)b * 4096;
#pragma unroll
    for (int m = 0; m < 64; m++) out[m * 64 + d] = col[m];
    Ks[b * 64 + d] = ks;
}

// ---------------- flat exclusive prefix ---------------------------------------------------
__global__ __launch_bounds__(256) void prefix_flat(
    const float* __restrict__ KVs, const float* __restrict__ Ks,
    float* __restrict__ KVp, float* __restrict__ Ksp)
{
    int b = blockIdx.x;
    if (b < 128) {
        int e = b * 256 + threadIdx.x;
        int h = e >> 12, off = e & 4095;
        size_t base = (size_t)h * NC * 4096 + off;
        float run = 0.f;
#pragma unroll 4
        for (int c = 0; c < NC; c++) {
            size_t a = base + (size_t)c * 4096;
            float v = KVs[a];
            KVp[a] = run;
            run += v;
        }
    } else {
        int e = (b - 128) * 256 + threadIdx.x;
        int h = e >> 6, d = e & 63;
        int base = h * NC * 64 + d;
        float run = 0.f;
#pragma unroll 4
        for (int c = 0; c < NC; c++) {
            int a = base + c * 64;
            float v = Ks[a];
            Ksp[a] = run;
            run += v;
        }
    }
}

// ---------------- within-chunk causal scan (fused hi/lo pack output) ----------------------
__global__ __launch_bounds__(64) void scan_kernel(
    const float* __restrict__ PQ, const float* __restrict__ PK,
    const float* __restrict__ QKV, const float* __restrict__ KVp,
    const float* __restrict__ Ksp,
    uint32_t* __restrict__ ApH, uint32_t* __restrict__ ApL)
{
    __shared__ float spq[CHUNK * 64], spk[CHUNK * 64], sv[CHUNK * 64];
    __shared__ float dp[CHUNK * 64];
    __shared__ float den[CHUNK];
    int b = blockIdx.x;
    int h = b / NC, c = b % NC;
    int d = threadIdx.x;
    int lane = d & 31, wid = d >> 5;
    int s0 = c * CHUNK;

    for (int i = d; i < CHUNK * 64; i += 64) {
        int ss = i >> 6, e = i & 63;
        spq[i] = PQ[(size_t)(s0 + ss) * DM + h * DH + e];
        spk[i] = PK[(size_t)(s0 + ss) * DM + h * DH + e];
        sv[i]  = QKV[(size_t)(s0 + ss) * NQKV + 1024 + h * DH + e];
    }
    float col[64];
    const float* kvp = KVp + (size_t)b * 4096;
#pragma unroll
    for (int m = 0; m < 64; m++) col[m] = kvp[m * 64 + d];
    float ksv = Ksp[b * 64 + d];
    __syncthreads();

    {
        float ks = ksv;
#pragma unroll
        for (int ss = 0; ss < CHUNK; ss++) {
            ks += spk[ss * 64 + d];
            dp[ss * 64 + d] = spq[ss * 64 + d] * ks;
        }
    }
    __syncthreads();
    {
#pragma unroll
        for (int r = 0; r < 16; r++) {
            int row = wid * 16 + r;
            float v = dp[row * 64 + lane] + dp[row * 64 + 32 + lane];
#pragma unroll
            for (int o = 16; o; o >>= 1) v += __shfl_xor_sync(0xffffffffu, v, o);
            if (lane == 0) den[row] = v + EPS_A;
        }
    }
    __syncthreads();

    const size_t krow = (size_t)((h * DH) >> 1) + (d >> 1);
    uint32_t* oh = ApH + krow * S_LEN + s0;
    uint32_t* ol = ApL + krow * S_LEN + s0;

    for (int ss = 0; ss < CHUNK; ss++) {
        float vd = sv[ss * 64 + d];
        float num = 0.f;
#pragma unroll
        for (int m = 0; m < 64; m++) {
            col[m] += spk[ss * 64 + m] * vd;
            num    += spq[ss * 64 + m] * col[m];
        }
        float val = num / den[ss];
        float part = __shfl_xor_sync(0xffffffffu, val, 1);
        if ((d & 1) == 0) {
            uint32_t H, L;
            pack_hl(val, part, H, L);
            oh[ss] = H; ol[ss] = L;
        }
    }
}

// ---------------- LayerNorm of (in0+in1+in2), fp32 out --------------------------------------
__global__ __launch_bounds__(128) void ln_kernel(
    const float* __restrict__ in0, const float* __restrict__ in1,
    const float* __restrict__ in2, const float* __restrict__ g,
    const float* __restrict__ be, float* __restrict__ out)
{
    __shared__ float sb[8];
    int row = blockIdx.x, tid = threadIdx.x;
    float4 v  = *(const float4*)(in0 + (size_t)row * DM + tid * 4);
    float4 v1 = *(const float4*)(in1 + (size_t)row * DM + tid * 4);
    float4 v2 = *(const float4*)(in2 + (size_t)row * DM + tid * 4);
    v.x += v1.x + v2.x; v.y += v1.y + v2.y; v.z += v1.z + v2.z; v.w += v1.w + v2.w;
    float s1 = v.x + v.y + v.z + v.w;
    float s2 = v.x * v.x + v.y * v.y + v.z * v.z + v.w * v.w;
    int lane = tid & 31, wid = tid >> 5;
#pragma unroll
    for (int o = 16; o; o >>= 1) {
        s1 += __shfl_xor_sync(0xffffffffu, s1, o);
        s2 += __shfl_xor_sync(0xffffffffu, s2, o);
    }
    if (lane == 0) { sb[wid] = s1; sb[4 + wid] = s2; }
    __syncthreads();
    s1 = sb[0] + sb[1] + sb[2] + sb[3];
    s2 = sb[4] + sb[5] + sb[6] + sb[7];
    float mu = s1 * (1.f / DM);
    float var = s2 * (1.f / DM) - mu * mu;
    float rs = rsqrtf(var + LN_EPS);
    float4 gv = *(const float4*)(g + tid * 4);
    float4 bv = *(const float4*)(be + tid * 4);
    float4 o;
    o.x = (v.x - mu) * rs * gv.x + bv.x;
    o.y = (v.y - mu) * rs * gv.y + bv.y;
    o.z = (v.z - mu) * rs * gv.z + bv.z;
    o.w = (v.w - mu) * rs * gv.w + bv.w;
    *(float4*)(out + (size_t)row * DM + tid * 4) = o;
}

// ---------------- fused LayerNorm(in0+in1+in2) + transpose-pack ------------------------------
__global__ __launch_bounds__(256) void ln_pack_kernel(
    const float* __restrict__ in0, const float* __restrict__ in1,
    const float* __restrict__ in2, const float* __restrict__ g,
    const float* __restrict__ be, float* __restrict__ out,
    uint32_t* __restrict__ outH, uint32_t* __restrict__ outL)
{
    __shared__ uint32_t sH[256 * 17], sL[256 * 17];
    int m0 = blockIdx.x * 16;
    int tid = threadIdx.x, lane = tid & 31, w = tid >> 5;

#pragma unroll
    for (int rr = 0; rr < 2; rr++) {
        int row = w * 2 + rr;
        const float4* rp0 = (const float4*)(in0 + (size_t)(m0 + row) * DM);
        const float4* rp1 = (const float4*)(in1 + (size_t)(m0 + row) * DM);
        const float4* rp2 = (const float4*)(in2 + (size_t)(m0 + row) * DM);
        float4 v[4];
        float s1 = 0.f, s2 = 0.f;
#pragma unroll
        for (int j = 0; j < 4; j++) {
            float4 a = rp0[lane + 32 * j];
            float4 b = rp1[lane + 32 * j];
            float4 cte = rp2[lane + 32 * j];
            a.x += b.x + cte.x; a.y += b.y + cte.y;
            a.z += b.z + cte.z; a.w += b.w + cte.w;
            v[j] = a;
            s1 += a.x + a.y + a.z + a.w;
            s2 += a.x * a.x + a.y * a.y + a.z * a.z + a.w * a.w;
        }
#pragma unroll
        for (int o = 16; o; o >>= 1) {
            s1 += __shfl_xor_sync(0xffffffffu, s1, o);
            s2 += __shfl_xor_sync(0xffffffffu, s2, o);
        }
        float mu = s1 * (1.f / DM);
        float var = s2 * (1.f / DM) - mu * mu;
        float rs = rsqrtf(var + LN_EPS);
        float4* op = (float4*)(out + (size_t)(m0 + row) * DM);
#pragma unroll
        for (int j = 0; j < 4; j++) {
            int fi = lane + 32 * j;
            float4 gv = ((const float4*)g)[fi];
            float4 bv = ((const float4*)be)[fi];
            float4 o;
            o.x = (v[j].x - mu) * rs * gv.x + bv.x;
            o.y = (v[j].y - mu) * rs * gv.y + bv.y;
            o.z = (v[j].z - mu) * rs * gv.z + bv.z;
            o.w = (v[j].w - mu) * rs * gv.w + bv.w;
            op[fi] = o;
            uint32_t H0, L0, H1, L1;
            pack_hl(o.x, o.y, H0, L0);
            pack_hl(o.z, o.w, H1, L1);
            int k2 = 2 * fi;
            sH[k2 * 17 + row] = H0;       sL[k2 * 17 + row] = L0;
            sH[(k2 + 1) * 17 + row] = H1; sL[(k2 + 1) * 17 + row] = L1;
        }
    }
    __syncthreads();

    uint32_t hb[16], lb[16];
#pragma unroll
    for (int m = 0; m < 16; m++) {
        hb[m] = sH[tid * 17 + m];
        lb[m] = sL[tid * 17 + m];
    }
    uint32_t* oh = outH + (size_t)tid * S_LEN + m0;
    uint32_t* ol = outL + (size_t)tid * S_LEN + m0;
#pragma unroll
    for (int m = 0; m < 16; m += 4) {
        *(uint4*)(oh + m) = make_uint4(hb[m], hb[m + 1], hb[m + 2], hb[m + 3]);
        *(uint4*)(ol + m) = make_uint4(lb[m], lb[m + 1], lb[m + 2], lb[m + 3]);
    }
}

// ---------------- launch ------------------------------------------------------------
extern "C" void kernel_launch(void* const* d_in, const int* in_sizes, int n_in,
                              void* d_out, int out_size)
{
    const float* x   = (const float*)d_in[0];
    const float* Wq  = (const float*)d_in[1];
    const float* Wk  = (const float*)d_in[2];
    const float* Wv  = (const float*)d_in[3];
    const float* Wo  = (const float*)d_in[4];
    const float* W1  = (const float*)d_in[5];
    const float* W2  = (const float*)d_in[6];
    const float* bq  = (const float*)d_in[7];
    const float* bk  = (const float*)d_in[8];
    const float* bv  = (const float*)d_in[9];
    const float* bo  = (const float*)d_in[10];
    const float* b1  = (const float*)d_in[11];
    const float* b2  = (const float*)d_in[12];
    const float* g1  = (const float*)d_in[13];
    const float* be1 = (const float*)d_in[14];
    const float* g2  = (const float*)d_in[15];
    const float* be2 = (const float*)d_in[16];
    const float* om  = (const float*)d_in[17];

    float *X, *T0, *T1, *QKV, *PQ, *PK, *KVs, *KVp, *Ks, *Ksp, *bqkv;
    uint32_t *XpH, *XpL, *ApH, *ApL, *FpH, *FpL;
    uint32_t *WqkvH, *WqkvL, *WoH, *WoL, *W1H, *W1L, *W2H, *W2L;
    cudaGetSymbolAddress((void**)&X,   g_X);
    cudaGetSymbolAddress((void**)&T0,  g_T0);
    cudaGetSymbolAddress((void**)&T1,  g_T1);
    cudaGetSymbolAddress((void**)&QKV, g_QKV);
    cudaGetSymbolAddress((void**)&PQ,  g_PQ);
    cudaGetSymbolAddress((void**)&PK,  g_PK);
    cudaGetSymbolAddress((void**)&KVs, g_KVs);
    cudaGetSymbolAddress((void**)&KVp, g_KVp);
    cudaGetSymbolAddress((void**)&Ks,  g_Ks);
    cudaGetSymbolAddress((void**)&Ksp, g_Ksp);
    cudaGetSymbolAddress((void**)&bqkv, g_bqkv);
    cudaGetSymbolAddress((void**)&XpH, g_XpH); cudaGetSymbolAddress((void**)&XpL, g_XpL);
    cudaGetSymbolAddress((void**)&ApH, g_ApH); cudaGetSymbolAddress((void**)&ApL, g_ApL);
    cudaGetSymbolAddress((void**)&FpH, g_FpH); cudaGetSymbolAddress((void**)&FpL, g_FpL);
    cudaGetSymbolAddress((void**)&WqkvH, g_WqkvH); cudaGetSymbolAddress((void**)&WqkvL, g_WqkvL);
    cudaGetSymbolAddress((void**)&WoH, g_WoH); cudaGetSymbolAddress((void**)&WoL, g_WoL);
    cudaGetSymbolAddress((void**)&W1H, g_W1H); cudaGetSymbolAddress((void**)&W1L, g_W1L);
    cudaGetSymbolAddress((void**)&W2H, g_W2H); cudaGetSymbolAddress((void**)&W2L, g_W2L);

    const int SMB64  = (2 * (2 * 16 * 136 + 2 * 16 * 72))  * 4;   // 53248
    const int SMB128 = (2 * (2 * 16 * 136 + 2 * 16 * 136)) * 4;   // 69632
    cudaFuncSetAttribute(hgemm<64, 0>,  cudaFuncAttributeMaxDynamicSharedMemorySize, SMB64);
    cudaFuncSetAttribute(hgemm<128, 0>, cudaFuncAttributeMaxDynamicSharedMemorySize, SMB128);
    cudaFuncSetAttribute(hgemm<128, 1>, cudaFuncAttributeMaxDynamicSharedMemorySize, SMB128);
    cudaFuncSetAttribute(hgemm_splitk,  cudaFuncAttributeMaxDynamicSharedMemorySize, SMB64);

    // ---- weight + bias packing ----
    {
        PackJobs jobs;
        for (int l = 0; l < NL; l++) {
            size_t oQKV = (size_t)l * (DM / 2) * NQKV;
            size_t oDM  = (size_t)l * (DM / 2) * DM;
            size_t o1   = (size_t)l * (DM / 2) * DFF;
            size_t o2   = (size_t)l * (DFF / 2) * DM;
            jobs.src[l*6+0] = Wq + (size_t)l*DM*DM;  jobs.dstH[l*6+0] = WqkvH + oQKV;        jobs.dstL[l*6+0] = WqkvL + oQKV;        jobs.ostr[l*6+0] = NQKV;
            jobs.src[l*6+1] = Wk + (size_t)l*DM*DM;  jobs.dstH[l*6+1] = WqkvH + oQKV + 512;  jobs.dstL[l*6+1] = WqkvL + oQKV + 512;  jobs.ostr[l*6+1] = NQKV;
            jobs.src[l*6+2] = Wv + (size_t)l*DM*DM;  jobs.dstH[l*6+2] = WqkvH + oQKV + 1024; jobs.dstL[l*6+2] = WqkvL + oQKV + 1024; jobs.ostr[l*6+2] = NQKV;
            jobs.src[l*6+3] = Wo + (size_t)l*DM*DM;  jobs.dstH[l*6+3] = WoH + oDM;           jobs.dstL[l*6+3] = WoL + oDM;           jobs.ostr[l*6+3] = DM;
            jobs.src[l*6+4] = W1 + (size_t)l*DM*DFF; jobs.dstH[l*6+4] = W1H + o1;            jobs.dstL[l*6+4] = W1L + o1;            jobs.ostr[l*6+4] = DFF;
            jobs.src[l*6+5] = W2 + (size_t)l*DFF*DM; jobs.dstH[l*6+5] = W2H + o2;            jobs.dstL[l*6+5] = W2L + o2;            jobs.ostr[l*6+5] = DM;
        }
        pack_all<<<NL * 1536, 256>>>(jobs);
        bias_qkv<<<NL * NQKV / 256, 256>>>(bq, bk, bv, bqkv);
    }

    cudaMemcpyAsync(X, x, sizeof(float) * S_LEN * DM, cudaMemcpyDeviceToDevice, 0);
    dim3 gpa(DM / 32, S_LEN / 32);
    pack_act<<<gpa, 256>>>(X, XpH, XpL, DM);

    dim3 gqkv(NQKV / 128, S_LEN / 128);      // 12x16 = 192 CTAs, NT=128
    dim3 gw1(DFF / 128, S_LEN / 128);        // 16x16 = 256 CTAs, NT=128
    dim3 gsplit(DM / 64, S_LEN / 128, 2);    // 8x16x2 = 256 CTAs, NT=64

    for (int l = 0; l < NL; l++) {
        size_t oQKV = (size_t)l * (DM / 2) * NQKV;
        size_t oDM  = (size_t)l * (DM / 2) * DM;
        size_t o1   = (size_t)l * (DM / 2) * DFF;
        size_t o2   = (size_t)l * (DFF / 2) * DM;
        const float* oml = om + (size_t)l * DH * MF;

        hgemm<128, 0><<<gqkv, 256, SMB128>>>(XpH, XpL, WqkvH + oQKV, WqkvL + oQKV,
                                             bqkv + l * NQKV, QKV, nullptr, nullptr,
                                             NQKV, DM);
        favor_kernel<<<dim3(S_LEN / 8, 2), 256>>>(QKV, oml, PQ, PK);
        chunk_sum_kernel<<<NH * NC, 64>>>(PK, QKV, KVs, Ks);
        prefix_flat<<<130, 256>>>(KVs, Ks, KVp, Ksp);
        scan_kernel<<<NH * NC, 64>>>(PQ, PK, QKV, KVp, Ksp, ApH, ApL);
        hgemm_splitk<<<gsplit, 256, SMB64>>>(ApH, ApL, WoH + oDM, WoL + oDM,
                                             bo + l * DM, T0, T1, DM, DM);
        ln_pack_kernel<<<S_LEN / 16, 256>>>(X, T0, T1, g1 + l * DM, be1 + l * DM,
                                            X, XpH, XpL);
        hgemm<128, 1><<<gw1, 256, SMB128>>>(XpH, XpL, W1H + o1, W1L + o1, b1 + l * DFF,
                                            nullptr, FpH, FpL, DFF, DM);
        hgemm_splitk<<<gsplit, 256, SMB64>>>(FpH, FpL, W2H + o2, W2L + o2,
                                             b2 + l * DM, T0, T1, DM, DFF);
        if (l == NL - 1) {
            ln_kernel<<<S_LEN, 128>>>(X, T0, T1, g2 + l * DM, be2 + l * DM, (float*)d_out);
        } else {
            ln_pack_kernel<<<S_LEN / 16, 256>>>(X, T0, T1, g2 + l * DM, be2 + l * DM,
                                                X, XpH, XpL);
        }
    }
}

// round 16
// speedup vs baseline: 1.0224x; 1.0224x over previous
#include <cuda_runtime.h>
#include <cuda_fp16.h>
#include <math.h>
#include <stdint.h>

// Problem constants
#define S_LEN 2048
#define DM    512
#define NH    8
#define DH    64
#define MF    64
#define DFF   2048
#define NL    2
#define NC    64
#define CHUNK 32
#define EPS_A 1e-6f
#define LN_EPS 1e-5f
#define NQKV  1536

// ---------------- scratch ----------------
__device__ float g_X [S_LEN*DM];
__device__ float g_T0[S_LEN*DM];
__device__ float g_T1[S_LEN*DM];
__device__ float g_QKV[S_LEN*NQKV];
__device__ float g_PQ[S_LEN*DM];
__device__ float g_PK[S_LEN*DM];
__device__ float g_KVs[NH*NC*DH*DH];
__device__ float g_KVp[NH*NC*DH*DH];
__device__ float g_Ks [NH*NC*DH];
__device__ float g_Ksp[NH*NC*DH];

// packed fp16 hi/lo operand buffers (K-major: [K/2][M])
__device__ uint32_t g_XpH[(DM/2)*S_LEN],  g_XpL[(DM/2)*S_LEN];
__device__ uint32_t g_ApH[(DM/2)*S_LEN],  g_ApL[(DM/2)*S_LEN];
__device__ uint32_t g_FpH[(DFF/2)*S_LEN], g_FpL[(DFF/2)*S_LEN];
__device__ uint32_t g_WqkvH[NL*(DM/2)*NQKV], g_WqkvL[NL*(DM/2)*NQKV];
__device__ uint32_t g_WoH[NL*(DM/2)*DM],  g_WoL[NL*(DM/2)*DM];
__device__ uint32_t g_W1H[NL*(DM/2)*DFF], g_W1L[NL*(DM/2)*DFF];
__device__ uint32_t g_W2H[NL*(DFF/2)*DM], g_W2L[NL*(DFF/2)*DM];
__device__ float    g_bqkv[NL*NQKV];

// ---------------- helpers ----------------
__device__ __forceinline__ uint32_t smem_u32(const void* p) {
    uint32_t a;
    asm("{ .reg .u64 t; cvta.to.shared.u64 t, %1; cvt.u32.u64 %0, t; }" : "=r"(a) : "l"(p));
    return a;
}
__device__ __forceinline__ void cp16(uint32_t dst, const void* src) {
    asm volatile("cp.async.cg.shared.global [%0], [%1], 16;" :: "r"(dst), "l"(src));
}
__device__ __forceinline__ void mma16816(float* d, const uint32_t* a,
                                         uint32_t b0, uint32_t b1) {
    asm volatile(
        "mma.sync.aligned.m16n8k16.row.col.f32.f16.f16.f32 "
        "{%0,%1,%2,%3}, {%4,%5,%6,%7}, {%8,%9}, {%0,%1,%2,%3};"
        : "+f"(d[0]), "+f"(d[1]), "+f"(d[2]), "+f"(d[3])
        : "r"(a[0]), "r"(a[1]), "r"(a[2]), "r"(a[3]), "r"(b0), "r"(b1));
}
__device__ __forceinline__ void pack_hl(float v0, float v1, uint32_t& hi, uint32_t& lo) {
    __half h0 = __float2half_rn(v0), h1 = __float2half_rn(v1);
    __half l0 = __float2half_rn(v0 - __half2float(h0));
    __half l1 = __float2half_rn(v1 - __half2float(h1));
    __half2 H = __halves2half2(h0, h1), L = __halves2half2(l0, l1);
    hi = *(uint32_t*)&H; lo = *(uint32_t*)&L;
}

// ---------------- merged weight pack ---------------------------------------------------
struct PackJobs {
    const float* src[NL * 6];
    uint32_t*    dstH[NL * 6];
    uint32_t*    dstL[NL * 6];
    int          ostr[NL * 6];
};
__global__ __launch_bounds__(256) void pack_all(PackJobs jobs) {
    int b = blockIdx.x;
    int l = b / 1536, r = b % 1536;
    int seg, local, N;
    if (r < 512)       { seg = r >> 7; local = r & 127;  N = DM;  }
    else if (r < 1024) { seg = 4;      local = r - 512;  N = DFF; }
    else               { seg = 5;      local = r - 1024; N = DM;  }
    int j = l * 6 + seg;
    const float* W = jobs.src[j];
    uint32_t* WH = jobs.dstH[j];
    uint32_t* WL = jobs.dstL[j];
    int ostr = jobs.ostr[j];
    int idx = local * 256 + threadIdx.x;
    int n4 = N / 4;
    int k2 = idx / n4;
    int n  = (idx % n4) * 4;
    float4 r0 = *(const float4*)(W + (size_t)(2 * k2) * N + n);
    float4 r1 = *(const float4*)(W + (size_t)(2 * k2 + 1) * N + n);
    uint4 H, L;
    pack_hl(r0.x, r1.x, H.x, L.x);
    pack_hl(r0.y, r1.y, H.y, L.y);
    pack_hl(r0.z, r1.z, H.z, L.z);
    pack_hl(r0.w, r1.w, H.w, L.w);
    *(uint4*)(WH + (size_t)k2 * ostr + n) = H;
    *(uint4*)(WL + (size_t)k2 * ostr + n) = L;
}

__global__ __launch_bounds__(256) void bias_qkv(
    const float* __restrict__ bq, const float* __restrict__ bk,
    const float* __restrict__ bv, float* __restrict__ out)
{
    int idx = blockIdx.x * 256 + threadIdx.x;
    int l = idx / NQKV, c = idx % NQKV;
    const float* src = (c < 512) ? bq : ((c < 1024) ? bk : bv);
    out[idx] = src[l * DM + (c & 511)];
}

// ---------------- activation pack (transpose): fp32 [M][K] -> [K/2][2048] ---------------
__global__ __launch_bounds__(256) void pack_act(
    const float* __restrict__ in, uint32_t* __restrict__ outH,
    uint32_t* __restrict__ outL, int K)
{
    __shared__ float s[32][33];
    int m0 = blockIdx.y * 32, k0 = blockIdx.x * 32;
    int tid = threadIdx.x;
    int r = tid >> 5, c = tid & 31;
#pragma unroll
    for (int j = 0; j < 4; j++)
        s[r + 8 * j][c] = in[(size_t)(m0 + r + 8 * j) * K + k0 + c];
    __syncthreads();
    int k2l = tid >> 5, m = tid & 31;
#pragma unroll
    for (int j = 0; j < 2; j++) {
        int kk = k2l + 8 * j;
        float v0 = s[m][2 * kk], v1 = s[m][2 * kk + 1];
        uint32_t H, L;
        pack_hl(v0, v1, H, L);
        size_t o = (size_t)(k0 / 2 + kk) * S_LEN + m0 + m;
        outH[o] = H; outL[o] = L;
    }
}

// ---------------- fp16 split-precision GEMM core (NT=64, one sync per chunk) -----------
template<int MODE>
__device__ __forceinline__ void hgemm_core(
    const uint32_t* __restrict__ Ahi, const uint32_t* __restrict__ Alo,
    const uint32_t* __restrict__ Bhi, const uint32_t* __restrict__ Blo,
    const float* __restrict__ bias,
    float* __restrict__ C, uint32_t* __restrict__ CpH, uint32_t* __restrict__ CpL,
    int N, int K, uint32_t* sm)
{
    constexpr int NT   = 64;
    constexpr int ASTR = 136;
    constexpr int BSTR = 72;
    constexpr int ASM  = 16 * ASTR;
    constexpr int BSM  = 16 * BSTR;
    constexpr int STG  = 2 * ASM + 2 * BSM;
    constexpr int NFR  = 4;
    constexpr int M    = S_LEN;

    const uint32_t smb = smem_u32(sm);
    const int tid = threadIdx.x;
    const int wid = tid >> 5, lane = tid & 31;
    const int lq = lane >> 2, lr = lane & 3;
    const int m0 = blockIdx.y * 128;
    const int n0 = blockIdx.x * NT;
    const int wm = (wid & 3) * 32;
    const int wn = (wid >> 2) * 32;

    float acc[2][NFR][4];
#pragma unroll
    for (int mi = 0; mi < 2; mi++)
#pragma unroll
        for (int ni = 0; ni < NFR; ni++)
#pragma unroll
            for (int e = 0; e < 4; e++) acc[mi][ni][e] = 0.f;

    const int KCH = K / 32;

#define PREFETCH(cc, ss) do {                                                  \
    uint32_t base = smb + (uint32_t)(ss) * STG * 4;                            \
    const uint32_t* Ah = Ahi + (size_t)((cc) * 16) * M + m0;                   \
    const uint32_t* Al = Alo + (size_t)((cc) * 16) * M + m0;                   \
    _Pragma("unroll")                                                          \
    for (int i = 0; i < 2; i++) {                                              \
        int idx = tid + i * 256; int rr = idx >> 5; int c4 = (idx & 31) * 4;   \
        cp16(base + (uint32_t)(rr * ASTR + c4) * 4, Ah + (size_t)rr * M + c4); \
        cp16(base + (uint32_t)(ASM + rr * ASTR + c4) * 4, Al + (size_t)rr * M + c4); \
    }                                                                          \
    {                                                                          \
        int rr = tid >> 4; int c4 = (tid & 15) * 4;                            \
        const uint32_t* Bh = Bhi + (size_t)((cc) * 16) * N + n0;               \
        const uint32_t* Bl = Blo + (size_t)((cc) * 16) * N + n0;               \
        cp16(base + (uint32_t)(2 * ASM + rr * BSTR + c4) * 4, Bh + (size_t)rr * N + c4); \
        cp16(base + (uint32_t)(2 * ASM + BSM + rr * BSTR + c4) * 4, Bl + (size_t)rr * N + c4); \
    }                                                                          \
    asm volatile("cp.async.commit_group;" ::: "memory");                       \
} while (0)

    PREFETCH(0, 0);

    for (int c = 0; c < KCH; c++) {
        const int s = c & 1;
        asm volatile("cp.async.wait_group 0;" ::: "memory");
        __syncthreads();
        if (c + 1 < KCH) PREFETCH(c + 1, s ^ 1);

        const uint32_t* sAh = sm + s * STG;
        const uint32_t* sAl = sAh + ASM;
        const uint32_t* sBh = sAh + 2 * ASM;
        const uint32_t* sBl = sBh + BSM;

#pragma unroll
        for (int st = 0; st < 2; st++) {
            const int kb = st * 8;
            uint32_t ah[2][4], al[2][4];
#pragma unroll
            for (int mi = 0; mi < 2; mi++) {
                int m = wm + mi * 16 + lq;
                int i0 = (kb + lr) * ASTR + m;
                int i1 = (kb + 4 + lr) * ASTR + m;
                ah[mi][0] = sAh[i0];     ah[mi][1] = sAh[i0 + 8];
                ah[mi][2] = sAh[i1];     ah[mi][3] = sAh[i1 + 8];
                al[mi][0] = sAl[i0];     al[mi][1] = sAl[i0 + 8];
                al[mi][2] = sAl[i1];     al[mi][3] = sAl[i1 + 8];
            }
#pragma unroll
            for (int ni = 0; ni < NFR; ni++) {
                int n = wn + ni * 8 + lq;
                int j0 = (kb + lr) * BSTR + n;
                int j1 = (kb + 4 + lr) * BSTR + n;
                uint32_t bh0 = sBh[j0], bh1 = sBh[j1];
                uint32_t bl0 = sBl[j0], bl1 = sBl[j1];
#pragma unroll
                for (int mi = 0; mi < 2; mi++) {
                    mma16816(acc[mi][ni], ah[mi], bh0, bh1);
                    mma16816(acc[mi][ni], ah[mi], bl0, bl1);
                    mma16816(acc[mi][ni], al[mi], bh0, bh1);
                }
            }
        }
        // no trailing sync: next iteration's top sync orders compute(s) before prefetch->s
    }
#undef PREFETCH

#pragma unroll
    for (int mi = 0; mi < 2; mi++) {
        int r = m0 + wm + mi * 16 + lq;
#pragma unroll
        for (int ni = 0; ni < NFR; ni++) {
            int cc = n0 + wn + ni * 8 + lr * 2;
            float b0 = bias ? __ldg(bias + cc) : 0.f;
            float b1 = bias ? __ldg(bias + cc + 1) : 0.f;
            float v00 = acc[mi][ni][0] + b0, v01 = acc[mi][ni][1] + b1;
            float v10 = acc[mi][ni][2] + b0, v11 = acc[mi][ni][3] + b1;
            if (MODE == 0) {
                *(float2*)(C + (size_t)r * N + cc)       = make_float2(v00, v01);
                *(float2*)(C + (size_t)(r + 8) * N + cc) = make_float2(v10, v11);
            } else {
                v00 = fmaxf(v00, 0.f); v01 = fmaxf(v01, 0.f);
                v10 = fmaxf(v10, 0.f); v11 = fmaxf(v11, 0.f);
                uint32_t H0, L0, H1, L1;
                pack_hl(v00, v01, H0, L0);
                pack_hl(v10, v11, H1, L1);
                size_t o = (size_t)(cc >> 1) * M + r;
                CpH[o] = H0;     CpL[o] = L0;
                CpH[o + 8] = H1; CpL[o + 8] = L1;
            }
        }
    }
}

template<int MODE>
__global__ __launch_bounds__(256, 3) void hgemm(
    const uint32_t* __restrict__ Ahi, const uint32_t* __restrict__ Alo,
    const uint32_t* __restrict__ Bhi, const uint32_t* __restrict__ Blo,
    const float* __restrict__ bias,
    float* __restrict__ C, uint32_t* __restrict__ CpH, uint32_t* __restrict__ CpL,
    int N, int K)
{
    extern __shared__ uint32_t sm[];
    hgemm_core<MODE>(Ahi, Alo, Bhi, Blo, bias, C, CpH, CpL, N, K, sm);
}

// split-K x2: blockIdx.z selects K-half; z=0 gets bias; partials to C0/C1.
__global__ __launch_bounds__(256, 3) void hgemm_splitk(
    const uint32_t* __restrict__ Ahi, const uint32_t* __restrict__ Alo,
    const uint32_t* __restrict__ Bhi, const uint32_t* __restrict__ Blo,
    const float* __restrict__ bias,
    float* __restrict__ C0, float* __restrict__ C1,
    int N, int Kfull)
{
    extern __shared__ uint32_t sm[];
    const int Ksp = Kfull / 2;
    const int z = blockIdx.z;
    const size_t aoff = (size_t)z * (Ksp / 2) * S_LEN;
    const size_t boff = (size_t)z * (Ksp / 2) * N;
    hgemm_core<0>(Ahi + aoff, Alo + aoff, Bhi + boff, Blo + boff,
                  z == 0 ? bias : nullptr,
                  z == 0 ? C0 : C1, nullptr, nullptr, N, Ksp, sm);
}

// ---------------- FAVOR+ feature map ----------------------------------------------------
__global__ __launch_bounds__(256) void favor_kernel(
    const float* __restrict__ QKV, const float* __restrict__ omega,
    float* __restrict__ PQ, float* __restrict__ PK)
{
    __shared__ float som[DH * MF];
    __shared__ float sx[8 * 8 * 64];
    float* P = blockIdx.y ? PK : PQ;
    const float* X = QKV + blockIdx.y * 512;
    int tid = threadIdx.x, w = tid >> 5, lane = tid & 31;
    for (int i = tid; i < DH * MF; i += 256) som[i] = omega[i];

    int s = blockIdx.x * 8 + w;
    const float SC = 0.35355339059327379f;
    const float* xrow = X + (size_t)s * NQKV;

    float nrm[8];
#pragma unroll
    for (int r = 0; r < 8; r++) {
        float x0 = xrow[r * 64 + lane] * SC;
        float x1 = xrow[r * 64 + 32 + lane] * SC;
        sx[w * 512 + r * 64 + lane] = x0;
        sx[w * 512 + r * 64 + 32 + lane] = x1;
        float n = x0 * x0 + x1 * x1;
#pragma unroll
        for (int o = 16; o; o >>= 1) n += __shfl_xor_sync(0xffffffffu, n, o);
        nrm[r] = n;
    }
    __syncthreads();

    float u0[8], u1[8];
#pragma unroll
    for (int r = 0; r < 8; r++) { u0[r] = 0.f; u1[r] = 0.f; }
#pragma unroll 8
    for (int d = 0; d < 64; d++) {
        float o0 = som[d * 64 + lane];
        float o1 = som[d * 64 + 32 + lane];
#pragma unroll
        for (int r = 0; r < 8; r++) {
            float xd = sx[w * 512 + r * 64 + d];
            u0[r] += xd * o0;
            u1[r] += xd * o1;
        }
    }
    float* prow = P + (size_t)s * DM;
#pragma unroll
    for (int r = 0; r < 8; r++) {
        float cst = -0.5f * nrm[r];
        prow[r * 64 + lane]      = expf(u0[r] + cst) * 0.125f;
        prow[r * 64 + 32 + lane] = expf(u1[r] + cst) * 0.125f;
    }
}

// ---------------- per-chunk sums ---------------------------------------------------------
__global__ __launch_bounds__(64) void chunk_sum_kernel(
    const float* __restrict__ PK, const float* __restrict__ QKV,
    float* __restrict__ KVs, float* __restrict__ Ks)
{
    __shared__ float spk[CHUNK * 64];
    __shared__ float sv [CHUNK * 64];
    int b = blockIdx.x;
    int h = b / NC, c = b % NC;
    int d = threadIdx.x;
    int s0 = c * CHUNK;
    for (int i = d; i < CHUNK * 64; i += 64) {
        int ss = i >> 6, e = i & 63;
        spk[i] = PK[(size_t)(s0 + ss) * DM + h * DH + e];
        sv[i]  = QKV[(size_t)(s0 + ss) * NQKV + 1024 + h * DH + e];
    }
    __syncthreads();
    float col[64];
#pragma unroll
    for (int m = 0; m < 64; m++) col[m] = 0.f;
    float ks = 0.f;
    for (int ss = 0; ss < CHUNK; ss++) {
        float vd = sv[ss * 64 + d];
        ks += spk[ss * 64 + d];
#pragma unroll
        for (int m = 0; m < 64; m++) col[m] += spk[ss * 64 + m] * vd;
    }
    float* out = KVs + (size_t)b * 4096;
#pragma unroll
    for (int m = 0; m < 64; m++) out[m * 64 + d] = col[m];
    Ks[b * 64 + d] = ks;
}

// ---------------- flat exclusive prefix ---------------------------------------------------
__global__ __launch_bounds__(256) void prefix_flat(
    const float* __restrict__ KVs, const float* __restrict__ Ks,
    float* __restrict__ KVp, float* __restrict__ Ksp)
{
    int b = blockIdx.x;
    if (b < 128) {
        int e = b * 256 + threadIdx.x;
        int h = e >> 12, off = e & 4095;
        size_t base = (size_t)h * NC * 4096 + off;
        float run = 0.f;
#pragma unroll 4
        for (int c = 0; c < NC; c++) {
            size_t a = base + (size_t)c * 4096;
            float v = KVs[a];
            KVp[a] = run;
            run += v;
        }
    } else {
        int e = (b - 128) * 256 + threadIdx.x;
        int h = e >> 6, d = e & 63;
        int base = h * NC * 64 + d;
        float run = 0.f;
#pragma unroll 4
        for (int c = 0; c < NC; c++) {
            int a = base + c * 64;
            float v = Ks[a];
            Ksp[a] = run;
            run += v;
        }
    }
}

// ---------------- within-chunk causal scan (fused hi/lo pack output) ----------------------
__global__ __launch_bounds__(64) void scan_kernel(
    const float* __restrict__ PQ, const float* __restrict__ PK,
    const float* __restrict__ QKV, const float* __restrict__ KVp,
    const float* __restrict__ Ksp,
    uint32_t* __restrict__ ApH, uint32_t* __restrict__ ApL)
{
    __shared__ float spq[CHUNK * 64], spk[CHUNK * 64], sv[CHUNK * 64];
    __shared__ float dp[CHUNK * 64];
    __shared__ float den[CHUNK];
    int b = blockIdx.x;
    int h = b / NC, c = b % NC;
    int d = threadIdx.x;
    int lane = d & 31, wid = d >> 5;
    int s0 = c * CHUNK;

    for (int i = d; i < CHUNK * 64; i += 64) {
        int ss = i >> 6, e = i & 63;
        spq[i] = PQ[(size_t)(s0 + ss) * DM + h * DH + e];
        spk[i] = PK[(size_t)(s0 + ss) * DM + h * DH + e];
        sv[i]  = QKV[(size_t)(s0 + ss) * NQKV + 1024 + h * DH + e];
    }
    float col[64];
    const float* kvp = KVp + (size_t)b * 4096;
#pragma unroll
    for (int m = 0; m < 64; m++) col[m] = kvp[m * 64 + d];
    float ksv = Ksp[b * 64 + d];
    __syncthreads();

    {
        float ks = ksv;
#pragma unroll
        for (int ss = 0; ss < CHUNK; ss++) {
            ks += spk[ss * 64 + d];
            dp[ss * 64 + d] = spq[ss * 64 + d] * ks;
        }
    }
    __syncthreads();
    {
#pragma unroll
        for (int r = 0; r < 16; r++) {
            int row = wid * 16 + r;
            float v = dp[row * 64 + lane] + dp[row * 64 + 32 + lane];
#pragma unroll
            for (int o = 16; o; o >>= 1) v += __shfl_xor_sync(0xffffffffu, v, o);
            if (lane == 0) den[row] = v + EPS_A;
        }
    }
    __syncthreads();

    const size_t krow = (size_t)((h * DH) >> 1) + (d >> 1);
    uint32_t* oh = ApH + krow * S_LEN + s0;
    uint32_t* ol = ApL + krow * S_LEN + s0;

    for (int ss = 0; ss < CHUNK; ss++) {
        float vd = sv[ss * 64 + d];
        float num = 0.f;
#pragma unroll
        for (int m = 0; m < 64; m++) {
            col[m] += spk[ss * 64 + m] * vd;
            num    += spq[ss * 64 + m] * col[m];
        }
        float val = num / den[ss];
        float part = __shfl_xor_sync(0xffffffffu, val, 1);
        if ((d & 1) == 0) {
            uint32_t H, L;
            pack_hl(val, part, H, L);
            oh[ss] = H; ol[ss] = L;
        }
    }
}

// ---------------- LayerNorm of (in0+in1+in2), fp32 out --------------------------------------
__global__ __launch_bounds__(128) void ln_kernel(
    const float* __restrict__ in0, const float* __restrict__ in1,
    const float* __restrict__ in2, const float* __restrict__ g,
    const float* __restrict__ be, float* __restrict__ out)
{
    __shared__ float sb[8];
    int row = blockIdx.x, tid = threadIdx.x;
    float4 v  = *(const float4*)(in0 + (size_t)row * DM + tid * 4);
    float4 v1 = *(const float4*)(in1 + (size_t)row * DM + tid * 4);
    float4 v2 = *(const float4*)(in2 + (size_t)row * DM + tid * 4);
    v.x += v1.x + v2.x; v.y += v1.y + v2.y; v.z += v1.z + v2.z; v.w += v1.w + v2.w;
    float s1 = v.x + v.y + v.z + v.w;
    float s2 = v.x * v.x + v.y * v.y + v.z * v.z + v.w * v.w;
    int lane = tid & 31, wid = tid >> 5;
#pragma unroll
    for (int o = 16; o; o >>= 1) {
        s1 += __shfl_xor_sync(0xffffffffu, s1, o);
        s2 += __shfl_xor_sync(0xffffffffu, s2, o);
    }
    if (lane == 0) { sb[wid] = s1; sb[4 + wid] = s2; }
    __syncthreads();
    s1 = sb[0] + sb[1] + sb[2] + sb[3];
    s2 = sb[4] + sb[5] + sb[6] + sb[7];
    float mu = s1 * (1.f / DM);
    float var = s2 * (1.f / DM) - mu * mu;
    float rs = rsqrtf(var + LN_EPS);
    float4 gv = *(const float4*)(g + tid * 4);
    float4 bv = *(const float4*)(be + tid * 4);
    float4 o;
    o.x = (v.x - mu) * rs * gv.x + bv.x;
    o.y = (v.y - mu) * rs * gv.y + bv.y;
    o.z = (v.z - mu) * rs * gv.z + bv.z;
    o.w = (v.w - mu) * rs * gv.w + bv.w;
    *(float4*)(out + (size_t)row * DM + tid * 4) = o;
}

// ---------------- fused LayerNorm(in0+in1+in2) + transpose-pack ------------------------------
__global__ __launch_bounds__(256) void ln_pack_kernel(
    const float* __restrict__ in0, const float* __restrict__ in1,
    const float* __restrict__ in2, const float* __restrict__ g,
    const float* __restrict__ be, float* __restrict__ out,
    uint32_t* __restrict__ outH, uint32_t* __restrict__ outL)
{
    __shared__ uint32_t sH[256 * 17], sL[256 * 17];
    int m0 = blockIdx.x * 16;
    int tid = threadIdx.x, lane = tid & 31, w = tid >> 5;

#pragma unroll
    for (int rr = 0; rr < 2; rr++) {
        int row = w * 2 + rr;
        const float4* rp0 = (const float4*)(in0 + (size_t)(m0 + row) * DM);
        const float4* rp1 = (const float4*)(in1 + (size_t)(m0 + row) * DM);
        const float4* rp2 = (const float4*)(in2 + (size_t)(m0 + row) * DM);
        float4 v[4];
        float s1 = 0.f, s2 = 0.f;
#pragma unroll
        for (int j = 0; j < 4; j++) {
            float4 a = rp0[lane + 32 * j];
            float4 b = rp1[lane + 32 * j];
            float4 cte = rp2[lane + 32 * j];
            a.x += b.x + cte.x; a.y += b.y + cte.y;
            a.z += b.z + cte.z; a.w += b.w + cte.w;
            v[j] = a;
            s1 += a.x + a.y + a.z + a.w;
            s2 += a.x * a.x + a.y * a.y + a.z * a.z + a.w * a.w;
        }
#pragma unroll
        for (int o = 16; o; o >>= 1) {
            s1 += __shfl_xor_sync(0xffffffffu, s1, o);
            s2 += __shfl_xor_sync(0xffffffffu, s2, o);
        }
        float mu = s1 * (1.f / DM);
        float var = s2 * (1.f / DM) - mu * mu;
        float rs = rsqrtf(var + LN_EPS);
        float4* op = (float4*)(out + (size_t)(m0 + row) * DM);
#pragma unroll
        for (int j = 0; j < 4; j++) {
            int fi = lane + 32 * j;
            float4 gv = ((const float4*)g)[fi];
            float4 bv = ((const float4*)be)[fi];
            float4 o;
            o.x = (v[j].x - mu) * rs * gv.x + bv.x;
            o.y = (v[j].y - mu) * rs * gv.y + bv.y;
            o.z = (v[j].z - mu) * rs * gv.z + bv.z;
            o.w = (v[j].w - mu) * rs * gv.w + bv.w;
            op[fi] = o;
            uint32_t H0, L0, H1, L1;
            pack_hl(o.x, o.y, H0, L0);
            pack_hl(o.z, o.w, H1, L1);
            int k2 = 2 * fi;
            sH[k2 * 17 + row] = H0;       sL[k2 * 17 + row] = L0;
            sH[(k2 + 1) * 17 + row] = H1; sL[(k2 + 1) * 17 + row] = L1;
        }
    }
    __syncthreads();

    uint32_t hb[16], lb[16];
#pragma unroll
    for (int m = 0; m < 16; m++) {
        hb[m] = sH[tid * 17 + m];
        lb[m] = sL[tid * 17 + m];
    }
    uint32_t* oh = outH + (size_t)tid * S_LEN + m0;
    uint32_t* ol = outL + (size_t)tid * S_LEN + m0;
#pragma unroll
    for (int m = 0; m < 16; m += 4) {
        *(uint4*)(oh + m) = make_uint4(hb[m], hb[m + 1], hb[m + 2], hb[m + 3]);
        *(uint4*)(ol + m) = make_uint4(lb[m], lb[m + 1], lb[m + 2], lb[m + 3]);
    }
}

// ---------------- launch ------------------------------------------------------------
extern "C" void kernel_launch(void* const* d_in, const int* in_sizes, int n_in,
                              void* d_out, int out_size)
{
    const float* x   = (const float*)d_in[0];
    const float* Wq  = (const float*)d_in[1];
    const float* Wk  = (const float*)d_in[2];
    const float* Wv  = (const float*)d_in[3];
    const float* Wo  = (const float*)d_in[4];
    const float* W1  = (const float*)d_in[5];
    const float* W2  = (const float*)d_in[6];
    const float* bq  = (const float*)d_in[7];
    const float* bk  = (const float*)d_in[8];
    const float* bv  = (const float*)d_in[9];
    const float* bo  = (const float*)d_in[10];
    const float* b1  = (const float*)d_in[11];
    const float* b2  = (const float*)d_in[12];
    const float* g1  = (const float*)d_in[13];
    const float* be1 = (const float*)d_in[14];
    const float* g2  = (const float*)d_in[15];
    const float* be2 = (const float*)d_in[16];
    const float* om  = (const float*)d_in[17];

    float *X, *T0, *T1, *QKV, *PQ, *PK, *KVs, *KVp, *Ks, *Ksp, *bqkv;
    uint32_t *XpH, *XpL, *ApH, *ApL, *FpH, *FpL;
    uint32_t *WqkvH, *WqkvL, *WoH, *WoL, *W1H, *W1L, *W2H, *W2L;
    cudaGetSymbolAddress((void**)&X,   g_X);
    cudaGetSymbolAddress((void**)&T0,  g_T0);
    cudaGetSymbolAddress((void**)&T1,  g_T1);
    cudaGetSymbolAddress((void**)&QKV, g_QKV);
    cudaGetSymbolAddress((void**)&PQ,  g_PQ);
    cudaGetSymbolAddress((void**)&PK,  g_PK);
    cudaGetSymbolAddress((void**)&KVs, g_KVs);
    cudaGetSymbolAddress((void**)&KVp, g_KVp);
    cudaGetSymbolAddress((void**)&Ks,  g_Ks);
    cudaGetSymbolAddress((void**)&Ksp, g_Ksp);
    cudaGetSymbolAddress((void**)&bqkv, g_bqkv);
    cudaGetSymbolAddress((void**)&XpH, g_XpH); cudaGetSymbolAddress((void**)&XpL, g_XpL);
    cudaGetSymbolAddress((void**)&ApH, g_ApH); cudaGetSymbolAddress((void**)&ApL, g_ApL);
    cudaGetSymbolAddress((void**)&FpH, g_FpH); cudaGetSymbolAddress((void**)&FpL, g_FpL);
    cudaGetSymbolAddress((void**)&WqkvH, g_WqkvH); cudaGetSymbolAddress((void**)&WqkvL, g_WqkvL);
    cudaGetSymbolAddress((void**)&WoH, g_WoH); cudaGetSymbolAddress((void**)&WoL, g_WoL);
    cudaGetSymbolAddress((void**)&W1H, g_W1H); cudaGetSymbolAddress((void**)&W1L, g_W1L);
    cudaGetSymbolAddress((void**)&W2H, g_W2H); cudaGetSymbolAddress((void**)&W2L, g_W2L);

    const int SMB = (2 * (2 * 16 * 136 + 2 * 16 * 72)) * 4;   // 53248
    cudaFuncSetAttribute(hgemm<0>,     cudaFuncAttributeMaxDynamicSharedMemorySize, SMB);
    cudaFuncSetAttribute(hgemm<1>,     cudaFuncAttributeMaxDynamicSharedMemorySize, SMB);
    cudaFuncSetAttribute(hgemm_splitk, cudaFuncAttributeMaxDynamicSharedMemorySize, SMB);

    // ---- weight + bias packing ----
    {
        PackJobs jobs;
        for (int l = 0; l < NL; l++) {
            size_t oQKV = (size_t)l * (DM / 2) * NQKV;
            size_t oDM  = (size_t)l * (DM / 2) * DM;
            size_t o1   = (size_t)l * (DM / 2) * DFF;
            size_t o2   = (size_t)l * (DFF / 2) * DM;
            jobs.src[l*6+0] = Wq + (size_t)l*DM*DM;  jobs.dstH[l*6+0] = WqkvH + oQKV;        jobs.dstL[l*6+0] = WqkvL + oQKV;        jobs.ostr[l*6+0] = NQKV;
            jobs.src[l*6+1] = Wk + (size_t)l*DM*DM;  jobs.dstH[l*6+1] = WqkvH + oQKV + 512;  jobs.dstL[l*6+1] = WqkvL + oQKV + 512;  jobs.ostr[l*6+1] = NQKV;
            jobs.src[l*6+2] = Wv + (size_t)l*DM*DM;  jobs.dstH[l*6+2] = WqkvH + oQKV + 1024; jobs.dstL[l*6+2] = WqkvL + oQKV + 1024; jobs.ostr[l*6+2] = NQKV;
            jobs.src[l*6+3] = Wo + (size_t)l*DM*DM;  jobs.dstH[l*6+3] = WoH + oDM;           jobs.dstL[l*6+3] = WoL + oDM;           jobs.ostr[l*6+3] = DM;
            jobs.src[l*6+4] = W1 + (size_t)l*DM*DFF; jobs.dstH[l*6+4] = W1H + o1;            jobs.dstL[l*6+4] = W1L + o1;            jobs.ostr[l*6+4] = DFF;
            jobs.src[l*6+5] = W2 + (size_t)l*DFF*DM; jobs.dstH[l*6+5] = W2H + o2;            jobs.dstL[l*6+5] = W2L + o2;            jobs.ostr[l*6+5] = DM;
        }
        pack_all<<<NL * 1536, 256>>>(jobs);
        bias_qkv<<<NL * NQKV / 256, 256>>>(bq, bk, bv, bqkv);
    }

    cudaMemcpyAsync(X, x, sizeof(float) * S_LEN * DM, cudaMemcpyDeviceToDevice, 0);
    dim3 gpa(DM / 32, S_LEN / 32);
    pack_act<<<gpa, 256>>>(X, XpH, XpL, DM);

    dim3 gqkv(NQKV / 64, S_LEN / 128);       // 24x16 = 384 CTAs
    dim3 gw1(DFF / 64, S_LEN / 128);         // 32x16 = 512 CTAs
    dim3 gsplit(DM / 64, S_LEN / 128, 2);    // 8x16x2 = 256 CTAs

    for (int l = 0; l < NL; l++) {
        const float* oml = om + (size_t)l * DH * MF;
        size_t oQKV = (size_t)l * (DM / 2) * NQKV;
        size_t oDM  = (size_t)l * (DM / 2) * DM;
        size_t o1   = (size_t)l * (DM / 2) * DFF;
        size_t o2   = (size_t)l * (DFF / 2) * DM;

        hgemm<0><<<gqkv, 256, SMB>>>(XpH, XpL, WqkvH + oQKV, WqkvL + oQKV,
                                     bqkv + l * NQKV, QKV, nullptr, nullptr, NQKV, DM);
        favor_kernel<<<dim3(S_LEN / 8, 2), 256>>>(QKV, oml, PQ, PK);
        chunk_sum_kernel<<<NH * NC, 64>>>(PK, QKV, KVs, Ks);
        prefix_flat<<<130, 256>>>(KVs, Ks, KVp, Ksp);
        scan_kernel<<<NH * NC, 64>>>(PQ, PK, QKV, KVp, Ksp, ApH, ApL);
        hgemm_splitk<<<gsplit, 256, SMB>>>(ApH, ApL, WoH + oDM, WoL + oDM,
                                           bo + l * DM, T0, T1, DM, DM);
        ln_pack_kernel<<<S_LEN / 16, 256>>>(X, T0, T1, g1 + l * DM, be1 + l * DM,
                                            X, XpH, XpL);
        hgemm<1><<<gw1, 256, SMB>>>(XpH, XpL, W1H + o1, W1L + o1, b1 + l * DFF,
                                    nullptr, FpH, FpL, DFF, DM);
        hgemm_splitk<<<gsplit, 256, SMB>>>(FpH, FpL, W2H + o2, W2L + o2,
                                           b2 + l * DM, T0, T1, DM, DFF);
        if (l == NL - 1) {
            ln_kernel<<<S_LEN, 128>>>(X, T0, T1, g2 + l * DM, be2 + l * DM, (float*)d_out);
        } else {
            ln_pack_kernel<<<S_LEN / 16, 256>>>(X, T0, T1, g2 + l * DM, be2 + l * DM,
                                                X, XpH, XpL);
        }
    }
}

// round 17
// speedup vs baseline: 1.0224x; 1.0001x over previous
#include <cuda_runtime.h>
#include <cuda_fp16.h>
#include <math.h>
#include <stdint.h>

// Problem constants
#define S_LEN 2048
#define DM    512
#define NH    8
#define DH    64
#define MF    64
#define DFF   2048
#define NL    2
#define NC    64
#define CHUNK 32
#define EPS_A 1e-6f
#define LN_EPS 1e-5f
#define NQKV  1536

// ---------------- scratch ----------------
__device__ float g_X [S_LEN*DM];
__device__ float g_T0[S_LEN*DM];
__device__ float g_T1[S_LEN*DM];
__device__ float g_QKV[S_LEN*NQKV];
__device__ float g_PQ[S_LEN*DM];
__device__ float g_PK[S_LEN*DM];
__device__ float g_KVs[NH*NC*DH*DH];
__device__ float g_KVp[NH*NC*DH*DH];
__device__ float g_Ks [NH*NC*DH];
__device__ float g_Ksp[NH*NC*DH];

// packed fp16 hi/lo operand buffers (K-major: [K/2][M])
__device__ uint32_t g_XpH[(DM/2)*S_LEN],  g_XpL[(DM/2)*S_LEN];
__device__ uint32_t g_ApH[(DM/2)*S_LEN],  g_ApL[(DM/2)*S_LEN];
__device__ uint32_t g_FpH[(DFF/2)*S_LEN], g_FpL[(DFF/2)*S_LEN];
__device__ uint32_t g_WqkvH[NL*(DM/2)*NQKV], g_WqkvL[NL*(DM/2)*NQKV];
__device__ uint32_t g_WoH[NL*(DM/2)*DM],  g_WoL[NL*(DM/2)*DM];
__device__ uint32_t g_W1H[NL*(DM/2)*DFF], g_W1L[NL*(DM/2)*DFF];
__device__ uint32_t g_W2H[NL*(DFF/2)*DM], g_W2L[NL*(DFF/2)*DM];
__device__ float    g_bqkv[NL*NQKV];

// ---------------- helpers ----------------
__device__ __forceinline__ uint32_t smem_u32(const void* p) {
    uint32_t a;
    asm("{ .reg .u64 t; cvta.to.shared.u64 t, %1; cvt.u32.u64 %0, t; }" : "=r"(a) : "l"(p));
    return a;
}
__device__ __forceinline__ void cp16(uint32_t dst, const void* src) {
    asm volatile("cp.async.cg.shared.global [%0], [%1], 16;" :: "r"(dst), "l"(src));
}
__device__ __forceinline__ void mma16816(float* d, const uint32_t* a,
                                         uint32_t b0, uint32_t b1) {
    asm volatile(
        "mma.sync.aligned.m16n8k16.row.col.f32.f16.f16.f32 "
        "{%0,%1,%2,%3}, {%4,%5,%6,%7}, {%8,%9}, {%0,%1,%2,%3};"
        : "+f"(d[0]), "+f"(d[1]), "+f"(d[2]), "+f"(d[3])
        : "r"(a[0]), "r"(a[1]), "r"(a[2]), "r"(a[3]), "r"(b0), "r"(b1));
}
__device__ __forceinline__ void pack_hl(float v0, float v1, uint32_t& hi, uint32_t& lo) {
    __half h0 = __float2half_rn(v0), h1 = __float2half_rn(v1);
    __half l0 = __float2half_rn(v0 - __half2float(h0));
    __half l1 = __float2half_rn(v1 - __half2float(h1));
    __half2 H = __halves2half2(h0, h1), L = __halves2half2(l0, l1);
    hi = *(uint32_t*)&H; lo = *(uint32_t*)&L;
}

// ---------------- merged weight pack ---------------------------------------------------
struct PackJobs {
    const float* src[NL * 6];
    uint32_t*    dstH[NL * 6];
    uint32_t*    dstL[NL * 6];
    int          ostr[NL * 6];
};
__global__ __launch_bounds__(256) void pack_all(PackJobs jobs) {
    int b = blockIdx.x;
    int l = b / 1536, r = b % 1536;
    int seg, local, N;
    if (r < 512)       { seg = r >> 7; local = r & 127;  N = DM;  }
    else if (r < 1024) { seg = 4;      local = r - 512;  N = DFF; }
    else               { seg = 5;      local = r - 1024; N = DM;  }
    int j = l * 6 + seg;
    const float* W = jobs.src[j];
    uint32_t* WH = jobs.dstH[j];
    uint32_t* WL = jobs.dstL[j];
    int ostr = jobs.ostr[j];
    int idx = local * 256 + threadIdx.x;
    int n4 = N / 4;
    int k2 = idx / n4;
    int n  = (idx % n4) * 4;
    float4 r0 = *(const float4*)(W + (size_t)(2 * k2) * N + n);
    float4 r1 = *(const float4*)(W + (size_t)(2 * k2 + 1) * N + n);
    uint4 H, L;
    pack_hl(r0.x, r1.x, H.x, L.x);
    pack_hl(r0.y, r1.y, H.y, L.y);
    pack_hl(r0.z, r1.z, H.z, L.z);
    pack_hl(r0.w, r1.w, H.w, L.w);
    *(uint4*)(WH + (size_t)k2 * ostr + n) = H;
    *(uint4*)(WL + (size_t)k2 * ostr + n) = L;
}

__global__ __launch_bounds__(256) void bias_qkv(
    const float* __restrict__ bq, const float* __restrict__ bk,
    const float* __restrict__ bv, float* __restrict__ out)
{
    int idx = blockIdx.x * 256 + threadIdx.x;
    int l = idx / NQKV, c = idx % NQKV;
    const float* src = (c < 512) ? bq : ((c < 1024) ? bk : bv);
    out[idx] = src[l * DM + (c & 511)];
}

// ---------------- activation pack (transpose): fp32 [M][K] -> [K/2][2048] ---------------
__global__ __launch_bounds__(256) void pack_act(
    const float* __restrict__ in, uint32_t* __restrict__ outH,
    uint32_t* __restrict__ outL, int K)
{
    __shared__ float s[32][33];
    int m0 = blockIdx.y * 32, k0 = blockIdx.x * 32;
    int tid = threadIdx.x;
    int r = tid >> 5, c = tid & 31;
#pragma unroll
    for (int j = 0; j < 4; j++)
        s[r + 8 * j][c] = in[(size_t)(m0 + r + 8 * j) * K + k0 + c];
    __syncthreads();
    int k2l = tid >> 5, m = tid & 31;
#pragma unroll
    for (int j = 0; j < 2; j++) {
        int kk = k2l + 8 * j;
        float v0 = s[m][2 * kk], v1 = s[m][2 * kk + 1];
        uint32_t H, L;
        pack_hl(v0, v1, H, L);
        size_t o = (size_t)(k0 / 2 + kk) * S_LEN + m0 + m;
        outH[o] = H; outL[o] = L;
    }
}

// ---------------- fp16 split-precision GEMM core (NT=64, NSTG stages) -------------------
template<int MODE, int NSTG>
__device__ __forceinline__ void hgemm_core(
    const uint32_t* __restrict__ Ahi, const uint32_t* __restrict__ Alo,
    const uint32_t* __restrict__ Bhi, const uint32_t* __restrict__ Blo,
    const float* __restrict__ bias,
    float* __restrict__ C, uint32_t* __restrict__ CpH, uint32_t* __restrict__ CpL,
    int N, int K, uint32_t* sm)
{
    constexpr int NT   = 64;
    constexpr int ASTR = 136;
    constexpr int BSTR = 72;
    constexpr int ASM  = 16 * ASTR;
    constexpr int BSM  = 16 * BSTR;
    constexpr int STG  = 2 * ASM + 2 * BSM;
    constexpr int NFR  = 4;
    constexpr int M    = S_LEN;

    const uint32_t smb = smem_u32(sm);
    const int tid = threadIdx.x;
    const int wid = tid >> 5, lane = tid & 31;
    const int lq = lane >> 2, lr = lane & 3;
    const int m0 = blockIdx.y * 128;
    const int n0 = blockIdx.x * NT;
    const int wm = (wid & 3) * 32;
    const int wn = (wid >> 2) * 32;

    float acc[2][NFR][4];
#pragma unroll
    for (int mi = 0; mi < 2; mi++)
#pragma unroll
        for (int ni = 0; ni < NFR; ni++)
#pragma unroll
            for (int e = 0; e < 4; e++) acc[mi][ni][e] = 0.f;

    const int KCH = K / 32;

#define PREFETCH(cc, ss) do {                                                  \
    uint32_t base = smb + (uint32_t)(ss) * STG * 4;                            \
    const uint32_t* Ah = Ahi + (size_t)((cc) * 16) * M + m0;                   \
    const uint32_t* Al = Alo + (size_t)((cc) * 16) * M + m0;                   \
    _Pragma("unroll")                                                          \
    for (int i = 0; i < 2; i++) {                                              \
        int idx = tid + i * 256; int rr = idx >> 5; int c4 = (idx & 31) * 4;   \
        cp16(base + (uint32_t)(rr * ASTR + c4) * 4, Ah + (size_t)rr * M + c4); \
        cp16(base + (uint32_t)(ASM + rr * ASTR + c4) * 4, Al + (size_t)rr * M + c4); \
    }                                                                          \
    {                                                                          \
        int rr = tid >> 4; int c4 = (tid & 15) * 4;                            \
        const uint32_t* Bh = Bhi + (size_t)((cc) * 16) * N + n0;               \
        const uint32_t* Bl = Blo + (size_t)((cc) * 16) * N + n0;               \
        cp16(base + (uint32_t)(2 * ASM + rr * BSTR + c4) * 4, Bh + (size_t)rr * N + c4); \
        cp16(base + (uint32_t)(2 * ASM + BSM + rr * BSTR + c4) * 4, Bl + (size_t)rr * N + c4); \
    }                                                                          \
    asm volatile("cp.async.commit_group;" ::: "memory");                       \
} while (0)

    if (NSTG == 3) {
        PREFETCH(0, 0);
        if (KCH > 1) PREFETCH(1, 1);
    } else {
        PREFETCH(0, 0);
    }

    for (int c = 0; c < KCH; c++) {
        const int s = (NSTG == 3) ? (c % 3) : (c & 1);
        if (NSTG == 3) {
            asm volatile("cp.async.wait_group 1;" ::: "memory");
        } else {
            asm volatile("cp.async.wait_group 0;" ::: "memory");
        }
        __syncthreads();
        if (NSTG == 3) {
            if (c + 2 < KCH) PREFETCH(c + 2, (c + 2) % 3);
            else asm volatile("cp.async.commit_group;" ::: "memory");  // keep group count
        } else {
            if (c + 1 < KCH) PREFETCH(c + 1, s ^ 1);
        }

        const uint32_t* sAh = sm + s * STG;
        const uint32_t* sAl = sAh + ASM;
        const uint32_t* sBh = sAh + 2 * ASM;
        const uint32_t* sBl = sBh + BSM;

#pragma unroll
        for (int st = 0; st < 2; st++) {
            const int kb = st * 8;
            uint32_t ah[2][4], al[2][4];
#pragma unroll
            for (int mi = 0; mi < 2; mi++) {
                int m = wm + mi * 16 + lq;
                int i0 = (kb + lr) * ASTR + m;
                int i1 = (kb + 4 + lr) * ASTR + m;
                ah[mi][0] = sAh[i0];     ah[mi][1] = sAh[i0 + 8];
                ah[mi][2] = sAh[i1];     ah[mi][3] = sAh[i1 + 8];
                al[mi][0] = sAl[i0];     al[mi][1] = sAl[i0 + 8];
                al[mi][2] = sAl[i1];     al[mi][3] = sAl[i1 + 8];
            }
#pragma unroll
            for (int ni = 0; ni < NFR; ni++) {
                int n = wn + ni * 8 + lq;
                int j0 = (kb + lr) * BSTR + n;
                int j1 = (kb + 4 + lr) * BSTR + n;
                uint32_t bh0 = sBh[j0], bh1 = sBh[j1];
                uint32_t bl0 = sBl[j0], bl1 = sBl[j1];
#pragma unroll
                for (int mi = 0; mi < 2; mi++) {
                    mma16816(acc[mi][ni], ah[mi], bh0, bh1);
                    mma16816(acc[mi][ni], ah[mi], bl0, bl1);
                    mma16816(acc[mi][ni], al[mi], bh0, bh1);
                }
            }
        }
        // no trailing sync (next top sync provides the ordering)
    }
#undef PREFETCH

#pragma unroll
    for (int mi = 0; mi < 2; mi++) {
        int r = m0 + wm + mi * 16 + lq;
#pragma unroll
        for (int ni = 0; ni < NFR; ni++) {
            int cc = n0 + wn + ni * 8 + lr * 2;
            float b0 = bias ? __ldg(bias + cc) : 0.f;
            float b1 = bias ? __ldg(bias + cc + 1) : 0.f;
            float v00 = acc[mi][ni][0] + b0, v01 = acc[mi][ni][1] + b1;
            float v10 = acc[mi][ni][2] + b0, v11 = acc[mi][ni][3] + b1;
            if (MODE == 0) {
                *(float2*)(C + (size_t)r * N + cc)       = make_float2(v00, v01);
                *(float2*)(C + (size_t)(r + 8) * N + cc) = make_float2(v10, v11);
            } else {
                v00 = fmaxf(v00, 0.f); v01 = fmaxf(v01, 0.f);
                v10 = fmaxf(v10, 0.f); v11 = fmaxf(v11, 0.f);
                uint32_t H0, L0, H1, L1;
                pack_hl(v00, v01, H0, L0);
                pack_hl(v10, v11, H1, L1);
                size_t o = (size_t)(cc >> 1) * M + r;
                CpH[o] = H0;     CpL[o] = L0;
                CpH[o + 8] = H1; CpL[o + 8] = L1;
            }
        }
    }
}

template<int MODE>
__global__ __launch_bounds__(256, 3) void hgemm(
    const uint32_t* __restrict__ Ahi, const uint32_t* __restrict__ Alo,
    const uint32_t* __restrict__ Bhi, const uint32_t* __restrict__ Blo,
    const float* __restrict__ bias,
    float* __restrict__ C, uint32_t* __restrict__ CpH, uint32_t* __restrict__ CpL,
    int N, int K)
{
    extern __shared__ uint32_t sm[];
    hgemm_core<MODE, 2>(Ahi, Alo, Bhi, Blo, bias, C, CpH, CpL, N, K, sm);
}

// split-K x2 (3-stage pipeline): blockIdx.z selects K-half; z=0 gets bias.
__global__ __launch_bounds__(256, 2) void hgemm_splitk(
    const uint32_t* __restrict__ Ahi, const uint32_t* __restrict__ Alo,
    const uint32_t* __restrict__ Bhi, const uint32_t* __restrict__ Blo,
    const float* __restrict__ bias,
    float* __restrict__ C0, float* __restrict__ C1,
    int N, int Kfull)
{
    extern __shared__ uint32_t sm[];
    const int Ksp = Kfull / 2;
    const int z = blockIdx.z;
    const size_t aoff = (size_t)z * (Ksp / 2) * S_LEN;
    const size_t boff = (size_t)z * (Ksp / 2) * N;
    hgemm_core<0, 3>(Ahi + aoff, Alo + aoff, Bhi + boff, Blo + boff,
                     z == 0 ? bias : nullptr,
                     z == 0 ? C0 : C1, nullptr, nullptr, N, Ksp, sm);
}

// ---------------- FAVOR+ feature map ----------------------------------------------------
__global__ __launch_bounds__(256) void favor_kernel(
    const float* __restrict__ QKV, const float* __restrict__ omega,
    float* __restrict__ PQ, float* __restrict__ PK)
{
    __shared__ float som[DH * MF];
    __shared__ float sx[8 * 8 * 64];
    float* P = blockIdx.y ? PK : PQ;
    const float* X = QKV + blockIdx.y * 512;
    int tid = threadIdx.x, w = tid >> 5, lane = tid & 31;
    for (int i = tid; i < DH * MF; i += 256) som[i] = omega[i];

    int s = blockIdx.x * 8 + w;
    const float SC = 0.35355339059327379f;
    const float* xrow = X + (size_t)s * NQKV;

    float nrm[8];
#pragma unroll
    for (int r = 0; r < 8; r++) {
        float x0 = xrow[r * 64 + lane] * SC;
        float x1 = xrow[r * 64 + 32 + lane] * SC;
        sx[w * 512 + r * 64 + lane] = x0;
        sx[w * 512 + r * 64 + 32 + lane] = x1;
        float n = x0 * x0 + x1 * x1;
#pragma unroll
        for (int o = 16; o; o >>= 1) n += __shfl_xor_sync(0xffffffffu, n, o);
        nrm[r] = n;
    }
    __syncthreads();

    float u0[8], u1[8];
#pragma unroll
    for (int r = 0; r < 8; r++) { u0[r] = 0.f; u1[r] = 0.f; }
#pragma unroll 8
    for (int d = 0; d < 64; d++) {
        float o0 = som[d * 64 + lane];
        float o1 = som[d * 64 + 32 + lane];
#pragma unroll
        for (int r = 0; r < 8; r++) {
            float xd = sx[w * 512 + r * 64 + d];
            u0[r] += xd * o0;
            u1[r] += xd * o1;
        }
    }
    float* prow = P + (size_t)s * DM;
#pragma unroll
    for (int r = 0; r < 8; r++) {
        float cst = -0.5f * nrm[r];
        prow[r * 64 + lane]      = expf(u0[r] + cst) * 0.125f;
        prow[r * 64 + 32 + lane] = expf(u1[r] + cst) * 0.125f;
    }
}

// ---------------- per-chunk sums ---------------------------------------------------------
__global__ __launch_bounds__(64) void chunk_sum_kernel(
    const float* __restrict__ PK, const float* __restrict__ QKV,
    float* __restrict__ KVs, float* __restrict__ Ks)
{
    __shared__ float spk[CHUNK * 64];
    __shared__ float sv [CHUNK * 64];
    int b = blockIdx.x;
    int h = b / NC, c = b % NC;
    int d = threadIdx.x;
    int s0 = c * CHUNK;
    for (int i = d; i < CHUNK * 64; i += 64) {
        int ss = i >> 6, e = i & 63;
        spk[i] = PK[(size_t)(s0 + ss) * DM + h * DH + e];
        sv[i]  = QKV[(size_t)(s0 + ss) * NQKV + 1024 + h * DH + e];
    }
    __syncthreads();
    float col[64];
#pragma unroll
    for (int m = 0; m < 64; m++) col[m] = 0.f;
    float ks = 0.f;
    for (int ss = 0; ss < CHUNK; ss++) {
        float vd = sv[ss * 64 + d];
        ks += spk[ss * 64 + d];
#pragma unroll
        for (int m = 0; m < 64; m++) col[m] += spk[ss * 64 + m] * vd;
    }
    float* out = KVs + (size_t)b * 4096;
#pragma unroll
    for (int m = 0; m < 64; m++) out[m * 64 + d] = col[m];
    Ks[b * 64 + d] = ks;
}

// ---------------- flat exclusive prefix ---------------------------------------------------
__global__ __launch_bounds__(256) void prefix_flat(
    const float* __restrict__ KVs, const float* __restrict__ Ks,
    float* __restrict__ KVp, float* __restrict__ Ksp)
{
    int b = blockIdx.x;
    if (b < 128) {
        int e = b * 256 + threadIdx.x;
        int h = e >> 12, off = e & 4095;
        size_t base = (size_t)h * NC * 4096 + off;
        float run = 0.f;
#pragma unroll 4
        for (int c = 0; c < NC; c++) {
            size_t a = base + (size_t)c * 4096;
            float v = KVs[a];
            KVp[a] = run;
            run += v;
        }
    } else {
        int e = (b - 128) * 256 + threadIdx.x;
        int h = e >> 6, d = e & 63;
        int base = h * NC * 64 + d;
        float run = 0.f;
#pragma unroll 4
        for (int c = 0; c < NC; c++) {
            int a = base + c * 64;
            float v = Ks[a];
            Ksp[a] = run;
            run += v;
        }
    }
}

// ---------------- within-chunk causal scan (fused hi/lo pack output) ----------------------
__global__ __launch_bounds__(64) void scan_kernel(
    const float* __restrict__ PQ, const float* __restrict__ PK,
    const float* __restrict__ QKV, const float* __restrict__ KVp,
    const float* __restrict__ Ksp,
    uint32_t* __restrict__ ApH, uint32_t* __restrict__ ApL)
{
    __shared__ float spq[CHUNK * 64], spk[CHUNK * 64], sv[CHUNK * 64];
    __shared__ float dp[CHUNK * 64];
    __shared__ float den[CHUNK];
    int b = blockIdx.x;
    int h = b / NC, c = b % NC;
    int d = threadIdx.x;
    int lane = d & 31, wid = d >> 5;
    int s0 = c * CHUNK;

    for (int i = d; i < CHUNK * 64; i += 64) {
        int ss = i >> 6, e = i & 63;
        spq[i] = PQ[(size_t)(s0 + ss) * DM + h * DH + e];
        spk[i] = PK[(size_t)(s0 + ss) * DM + h * DH + e];
        sv[i]  = QKV[(size_t)(s0 + ss) * NQKV + 1024 + h * DH + e];
    }
    float col[64];
    const float* kvp = KVp + (size_t)b * 4096;
#pragma unroll
    for (int m = 0; m < 64; m++) col[m] = kvp[m * 64 + d];
    float ksv = Ksp[b * 64 + d];
    __syncthreads();

    {
        float ks = ksv;
#pragma unroll
        for (int ss = 0; ss < CHUNK; ss++) {
            ks += spk[ss * 64 + d];
            dp[ss * 64 + d] = spq[ss * 64 + d] * ks;
        }
    }
    __syncthreads();
    {
#pragma unroll
        for (int r = 0; r < 16; r++) {
            int row = wid * 16 + r;
            float v = dp[row * 64 + lane] + dp[row * 64 + 32 + lane];
#pragma unroll
            for (int o = 16; o; o >>= 1) v += __shfl_xor_sync(0xffffffffu, v, o);
            if (lane == 0) den[row] = v + EPS_A;
        }
    }
    __syncthreads();

    const size_t krow = (size_t)((h * DH) >> 1) + (d >> 1);
    uint32_t* oh = ApH + krow * S_LEN + s0;
    uint32_t* ol = ApL + krow * S_LEN + s0;

    for (int ss = 0; ss < CHUNK; ss++) {
        float vd = sv[ss * 64 + d];
        float num = 0.f;
#pragma unroll
        for (int m = 0; m < 64; m++) {
            col[m] += spk[ss * 64 + m] * vd;
            num    += spq[ss * 64 + m] * col[m];
        }
        float val = num / den[ss];
        float part = __shfl_xor_sync(0xffffffffu, val, 1);
        if ((d & 1) == 0) {
            uint32_t H, L;
            pack_hl(val, part, H, L);
            oh[ss] = H; ol[ss] = L;
        }
    }
}

// ---------------- LayerNorm of (in0+in1+in2), fp32 out --------------------------------------
__global__ __launch_bounds__(128) void ln_kernel(
    const float* __restrict__ in0, const float* __restrict__ in1,
    const float* __restrict__ in2, const float* __restrict__ g,
    const float* __restrict__ be, float* __restrict__ out)
{
    __shared__ float sb[8];
    int row = blockIdx.x, tid = threadIdx.x;
    float4 v  = *(const float4*)(in0 + (size_t)row * DM + tid * 4);
    float4 v1 = *(const float4*)(in1 + (size_t)row * DM + tid * 4);
    float4 v2 = *(const float4*)(in2 + (size_t)row * DM + tid * 4);
    v.x += v1.x + v2.x; v.y += v1.y + v2.y; v.z += v1.z + v2.z; v.w += v1.w + v2.w;
    float s1 = v.x + v.y + v.z + v.w;
    float s2 = v.x * v.x + v.y * v.y + v.z * v.z + v.w * v.w;
    int lane = tid & 31, wid = tid >> 5;
#pragma unroll
    for (int o = 16; o; o >>= 1) {
        s1 += __shfl_xor_sync(0xffffffffu, s1, o);
        s2 += __shfl_xor_sync(0xffffffffu, s2, o);
    }
    if (lane == 0) { sb[wid] = s1; sb[4 + wid] = s2; }
    __syncthreads();
    s1 = sb[0] + sb[1] + sb[2] + sb[3];
    s2 = sb[4] + sb[5] + sb[6] + sb[7];
    float mu = s1 * (1.f / DM);
    float var = s2 * (1.f / DM) - mu * mu;
    float rs = rsqrtf(var + LN_EPS);
    float4 gv = *(const float4*)(g + tid * 4);
    float4 bv = *(const float4*)(be + tid * 4);
    float4 o;
    o.x = (v.x - mu) * rs * gv.x + bv.x;
    o.y = (v.y - mu) * rs * gv.y + bv.y;
    o.z = (v.z - mu) * rs * gv.z + bv.z;
    o.w = (v.w - mu) * rs * gv.w + bv.w;
    *(float4*)(out + (size_t)row * DM + tid * 4) = o;
}

// ---------------- fused LayerNorm(in0+in1+in2) + transpose-pack ------------------------------
__global__ __launch_bounds__(256) void ln_pack_kernel(
    const float* __restrict__ in0, const float* __restrict__ in1,
    const float* __restrict__ in2, const float* __restrict__ g,
    const float* __restrict__ be, float* __restrict__ out,
    uint32_t* __restrict__ outH, uint32_t* __restrict__ outL)
{
    __shared__ uint32_t sH[256 * 17], sL[256 * 17];
    int m0 = blockIdx.x * 16;
    int tid = threadIdx.x, lane = tid & 31, w = tid >> 5;

#pragma unroll
    for (int rr = 0; rr < 2; rr++) {
        int row = w * 2 + rr;
        const float4* rp0 = (const float4*)(in0 + (size_t)(m0 + row) * DM);
        const float4* rp1 = (const float4*)(in1 + (size_t)(m0 + row) * DM);
        const float4* rp2 = (const float4*)(in2 + (size_t)(m0 + row) * DM);
        float4 v[4];
        float s1 = 0.f, s2 = 0.f;
#pragma unroll
        for (int j = 0; j < 4; j++) {
            float4 a = rp0[lane + 32 * j];
            float4 b = rp1[lane + 32 * j];
            float4 cte = rp2[lane + 32 * j];
            a.x += b.x + cte.x; a.y += b.y + cte.y;
            a.z += b.z + cte.z; a.w += b.w + cte.w;
            v[j] = a;
            s1 += a.x + a.y + a.z + a.w;
            s2 += a.x * a.x + a.y * a.y + a.z * a.z + a.w * a.w;
        }
#pragma unroll
        for (int o = 16; o; o >>= 1) {
            s1 += __shfl_xor_sync(0xffffffffu, s1, o);
            s2 += __shfl_xor_sync(0xffffffffu, s2, o);
        }
        float mu = s1 * (1.f / DM);
        float var = s2 * (1.f / DM) - mu * mu;
        float rs = rsqrtf(var + LN_EPS);
        float4* op = (float4*)(out + (size_t)(m0 + row) * DM);
#pragma unroll
        for (int j = 0; j < 4; j++) {
            int fi = lane + 32 * j;
            float4 gv = ((const float4*)g)[fi];
            float4 bv = ((const float4*)be)[fi];
            float4 o;
            o.x = (v[j].x - mu) * rs * gv.x + bv.x;
            o.y = (v[j].y - mu) * rs * gv.y + bv.y;
            o.z = (v[j].z - mu) * rs * gv.z + bv.z;
            o.w = (v[j].w - mu) * rs * gv.w + bv.w;
            op[fi] = o;
            uint32_t H0, L0, H1, L1;
            pack_hl(o.x, o.y, H0, L0);
            pack_hl(o.z, o.w, H1, L1);
            int k2 = 2 * fi;
            sH[k2 * 17 + row] = H0;       sL[k2 * 17 + row] = L0;
            sH[(k2 + 1) * 17 + row] = H1; sL[(k2 + 1) * 17 + row] = L1;
        }
    }
    __syncthreads();

    uint32_t hb[16], lb[16];
#pragma unroll
    for (int m = 0; m < 16; m++) {
        hb[m] = sH[tid * 17 + m];
        lb[m] = sL[tid * 17 + m];
    }
    uint32_t* oh = outH + (size_t)tid * S_LEN + m0;
    uint32_t* ol = outL + (size_t)tid * S_LEN + m0;
#pragma unroll
    for (int m = 0; m < 16; m += 4) {
        *(uint4*)(oh + m) = make_uint4(hb[m], hb[m + 1], hb[m + 2], hb[m + 3]);
        *(uint4*)(ol + m) = make_uint4(lb[m], lb[m + 1], lb[m + 2], lb[m + 3]);
    }
}

// ---------------- launch ------------------------------------------------------------
extern "C" void kernel_launch(void* const* d_in, const int* in_sizes, int n_in,
                              void* d_out, int out_size)
{
    const float* x   = (const float*)d_in[0];
    const float* Wq  = (const float*)d_in[1];
    const float* Wk  = (const float*)d_in[2];
    const float* Wv  = (const float*)d_in[3];
    const float* Wo  = (const float*)d_in[4];
    const float* W1  = (const float*)d_in[5];
    const float* W2  = (const float*)d_in[6];
    const float* bq  = (const float*)d_in[7];
    const float* bk  = (const float*)d_in[8];
    const float* bv  = (const float*)d_in[9];
    const float* bo  = (const float*)d_in[10];
    const float* b1  = (const float*)d_in[11];
    const float* b2  = (const float*)d_in[12];
    const float* g1  = (const float*)d_in[13];
    const float* be1 = (const float*)d_in[14];
    const float* g2  = (const float*)d_in[15];
    const float* be2 = (const float*)d_in[16];
    const float* om  = (const float*)d_in[17];

    float *X, *T0, *T1, *QKV, *PQ, *PK, *KVs, *KVp, *Ks, *Ksp, *bqkv;
    uint32_t *XpH, *XpL, *ApH, *ApL, *FpH, *FpL;
    uint32_t *WqkvH, *WqkvL, *WoH, *WoL, *W1H, *W1L, *W2H, *W2L;
    cudaGetSymbolAddress((void**)&X,   g_X);
    cudaGetSymbolAddress((void**)&T0,  g_T0);
    cudaGetSymbolAddress((void**)&T1,  g_T1);
    cudaGetSymbolAddress((void**)&QKV, g_QKV);
    cudaGetSymbolAddress((void**)&PQ,  g_PQ);
    cudaGetSymbolAddress((void**)&PK,  g_PK);
    cudaGetSymbolAddress((void**)&KVs, g_KVs);
    cudaGetSymbolAddress((void**)&KVp, g_KVp);
    cudaGetSymbolAddress((void**)&Ks,  g_Ks);
    cudaGetSymbolAddress((void**)&Ksp, g_Ksp);
    cudaGetSymbolAddress((void**)&bqkv, g_bqkv);
    cudaGetSymbolAddress((void**)&XpH, g_XpH); cudaGetSymbolAddress((void**)&XpL, g_XpL);
    cudaGetSymbolAddress((void**)&ApH, g_ApH); cudaGetSymbolAddress((void**)&ApL, g_ApL);
    cudaGetSymbolAddress((void**)&FpH, g_FpH); cudaGetSymbolAddress((void**)&FpL, g_FpL);
    cudaGetSymbolAddress((void**)&WqkvH, g_WqkvH); cudaGetSymbolAddress((void**)&WqkvL, g_WqkvL);
    cudaGetSymbolAddress((void**)&WoH, g_WoH); cudaGetSymbolAddress((void**)&WoL, g_WoL);
    cudaGetSymbolAddress((void**)&W1H, g_W1H); cudaGetSymbolAddress((void**)&W1L, g_W1L);
    cudaGetSymbolAddress((void**)&W2H, g_W2H); cudaGetSymbolAddress((void**)&W2L, g_W2L);

    const int SMB  = (2 * (2 * 16 * 136 + 2 * 16 * 72)) * 4;   // 53248 (2-stage)
    const int SMB3 = (3 * (2 * 16 * 136 + 2 * 16 * 72)) * 4;   // 79872 (3-stage)
    cudaFuncSetAttribute(hgemm<0>,     cudaFuncAttributeMaxDynamicSharedMemorySize, SMB);
    cudaFuncSetAttribute(hgemm<1>,     cudaFuncAttributeMaxDynamicSharedMemorySize, SMB);
    cudaFuncSetAttribute(hgemm_splitk, cudaFuncAttributeMaxDynamicSharedMemorySize, SMB3);

    // ---- weight + bias packing ----
    {
        PackJobs jobs;
        for (int l = 0; l < NL; l++) {
            size_t oQKV = (size_t)l * (DM / 2) * NQKV;
            size_t oDM  = (size_t)l * (DM / 2) * DM;
            size_t o1   = (size_t)l * (DM / 2) * DFF;
            size_t o2   = (size_t)l * (DFF / 2) * DM;
            jobs.src[l*6+0] = Wq + (size_t)l*DM*DM;  jobs.dstH[l*6+0] = WqkvH + oQKV;        jobs.dstL[l*6+0] = WqkvL + oQKV;        jobs.ostr[l*6+0] = NQKV;
            jobs.src[l*6+1] = Wk + (size_t)l*DM*DM;  jobs.dstH[l*6+1] = WqkvH + oQKV + 512;  jobs.dstL[l*6+1] = WqkvL + oQKV + 512;  jobs.ostr[l*6+1] = NQKV;
            jobs.src[l*6+2] = Wv + (size_t)l*DM*DM;  jobs.dstH[l*6+2] = WqkvH + oQKV + 1024; jobs.dstL[l*6+2] = WqkvL + oQKV + 1024; jobs.ostr[l*6+2] = NQKV;
            jobs.src[l*6+3] = Wo + (size_t)l*DM*DM;  jobs.dstH[l*6+3] = WoH + oDM;           jobs.dstL[l*6+3] = WoL + oDM;           jobs.ostr[l*6+3] = DM;
            jobs.src[l*6+4] = W1 + (size_t)l*DM*DFF; jobs.dstH[l*6+4] = W1H + o1;            jobs.dstL[l*6+4] = W1L + o1;            jobs.ostr[l*6+4] = DFF;
            jobs.src[l*6+5] = W2 + (size_t)l*DFF*DM; jobs.dstH[l*6+5] = W2H + o2;            jobs.dstL[l*6+5] = W2L + o2;            jobs.ostr[l*6+5] = DM;
        }
        pack_all<<<NL * 1536, 256>>>(jobs);
        bias_qkv<<<NL * NQKV / 256, 256>>>(bq, bk, bv, bqkv);
    }

    cudaMemcpyAsync(X, x, sizeof(float) * S_LEN * DM, cudaMemcpyDeviceToDevice, 0);
    dim3 gpa(DM / 32, S_LEN / 32);
    pack_act<<<gpa, 256>>>(X, XpH, XpL, DM);

    dim3 gqkv(NQKV / 64, S_LEN / 128);       // 24x16 = 384 CTAs
    dim3 gw1(DFF / 64, S_LEN / 128);         // 32x16 = 512 CTAs
    dim3 gsplit(DM / 64, S_LEN / 128, 2);    // 8x16x2 = 256 CTAs

    for (int l = 0; l < NL; l++) {
        const float* oml = om + (size_t)l * DH * MF;
        size_t oQKV = (size_t)l * (DM / 2) * NQKV;
        size_t oDM  = (size_t)l * (DM / 2) * DM;
        size_t o1   = (size_t)l * (DM / 2) * DFF;
        size_t o2   = (size_t)l * (DFF / 2) * DM;

        hgemm<0><<<gqkv, 256, SMB>>>(XpH, XpL, WqkvH + oQKV, WqkvL + oQKV,
                                     bqkv + l * NQKV, QKV, nullptr, nullptr, NQKV, DM);
        favor_kernel<<<dim3(S_LEN / 8, 2), 256>>>(QKV, oml, PQ, PK);
        chunk_sum_kernel<<<NH * NC, 64>>>(PK, QKV, KVs, Ks);
        prefix_flat<<<130, 256>>>(KVs, Ks, KVp, Ksp);
        scan_kernel<<<NH * NC, 64>>>(PQ, PK, QKV, KVp, Ksp, ApH, ApL);
        hgemm_splitk<<<gsplit, 256, SMB3>>>(ApH, ApL, WoH + oDM, WoL + oDM,
                                            bo + l * DM, T0, T1, DM, DM);
        ln_pack_kernel<<<S_LEN / 16, 256>>>(X, T0, T1, g1 + l * DM, be1 + l * DM,
                                            X, XpH, XpL);
        hgemm<1><<<gw1, 256, SMB>>>(XpH, XpL, W1H + o1, W1L + o1, b1 + l * DFF,
                                    nullptr, FpH, FpL, DFF, DM);
        hgemm_splitk<<<gsplit, 256, SMB3>>>(FpH, FpL, W2H + o2, W2L + o2,
                                            b2 + l * DM, T0, T1, DM, DFF);
        if (l == NL - 1) {
            ln_kernel<<<S_LEN, 128>>>(X, T0, T1, g2 + l * DM, be2 + l * DM, (float*)d_out);
        } else {
            ln_pack_kernel<<<S_LEN / 16, 256>>>(X, T0, T1, g2 + l * DM, be2 + l * DM,
                                                X, XpH, XpL);
        }
    }
}